// round 14
// baseline (speedup 1.0000x reference)
#include <cuda_runtime.h>
#include <cuda_bf16.h>
#include <cstdint>
#include <math.h>

#define Bc 8
#define Lc 512
#define Dmod 1024
#define Hc 16
#define Cc 4
#define Dkc 64
#define OUT_N  (Bc*Lc*Dmod)
#define AM_N   (Bc*Lc*Lc)
#define KL_OFF (OUT_N + AM_N)

__device__ float g_q[OUT_N];
__device__ float g_k[OUT_N];
__device__ float g_v[OUT_N];
__device__ float g_vt[OUT_N];
__device__ float g_ctx[OUT_N];
__device__ float g_wt[Dmod*Dmod];
__device__ float g_wt2[Dmod*Dmod];
__device__ float g_wt3[Dmod*Dmod];
__device__ float g_wt4[Dmod*Dmod];
__device__ float g_alv[Bc*Lc*Hc];
__device__ float g_alvh[Bc*Lc*Hc];
__device__ float g_cpq[Bc*Hc*Lc*Cc];
__device__ float g_cph[Bc*Hc*Lc*Cc];
__device__ float g_lpdf[Bc*Hc*Lc*Cc];
__device__ float g_pdf[Bc*Hc*Lc];
__device__ float g_wsum[Bc*Hc*Cc];
__device__ float g_attn[(size_t)Bc*Hc*Lc*Lc];
__device__ float g_gmax;

// ---------------- portable PTX helpers (sm_80+) ----------------
__device__ __forceinline__ uint32_t smem_to_u32(const void* p) {
  uint32_t a;
  asm("{ .reg .u64 t; cvta.to.shared.u64 t, %1; cvt.u32.u64 %0, t; }" : "=r"(a) : "l"(p));
  return a;
}
__device__ __forceinline__ void ldm_x4(uint32_t addr, uint32_t r[4]){
  asm volatile("ldmatrix.sync.aligned.m8n8.x4.shared.b16 {%0,%1,%2,%3}, [%4];"
    : "=r"(r[0]),"=r"(r[1]),"=r"(r[2]),"=r"(r[3]) : "r"(addr));
}
__device__ __forceinline__ void mma_bf16(float c[4], const uint32_t a[4], uint32_t b0, uint32_t b1){
  asm volatile("mma.sync.aligned.m16n8k16.row.col.f32.bf16.bf16.f32 "
    "{%0,%1,%2,%3}, {%4,%5,%6,%7}, {%8,%9}, {%0,%1,%2,%3};"
    : "+f"(c[0]),"+f"(c[1]),"+f"(c[2]),"+f"(c[3])
    : "r"(a[0]),"r"(a[1]),"r"(a[2]),"r"(a[3]), "r"(b0),"r"(b1));
}
__device__ __forceinline__ uint32_t packbf(float a, float b){ // lo16=a, hi16=b
  uint32_t r; asm("cvt.rn.bf16x2.f32 %0, %1, %2;" : "=r"(r) : "f"(b), "f"(a)); return r;
}
__device__ __forceinline__ void sts_v2(uint32_t a, uint32_t x, uint32_t y){
  asm volatile("st.shared.v2.b32 [%0], {%1, %2};" :: "r"(a), "r"(x), "r"(y) : "memory");
}
__device__ __forceinline__ float fexp(float x){
  x = fmaxf(x, -87.0f);
  float y = x * 1.4426950408889634f;
  float n = rintf(y);
  float f = (y - n) * 0.6931471805599453f;
  float p = 0.0013888889f;
  p = fmaf(p, f, 0.0083333333f);
  p = fmaf(p, f, 0.0416666667f);
  p = fmaf(p, f, 0.1666666667f);
  p = fmaf(p, f, 0.5f);
  p = fmaf(p, f, 1.0f);
  p = fmaf(p, f, 1.0f);
  int e = (int)n;
  return p * __int_as_float((e + 127) << 23);
}
__device__ __forceinline__ float wsum32(float v){
  #pragma unroll
  for (int o=16;o>0;o>>=1) v += __shfl_xor_sync(0xffffffffu, v, o);
  return v;
}
__device__ __forceinline__ float wmax32(float v){
  #pragma unroll
  for (int o=16;o>0;o>>=1) v = fmaxf(v, __shfl_xor_sync(0xffffffffu, v, o));
  return v;
}
__device__ __forceinline__ void cvt_sts_s(uint32_t hi_b, uint32_t lo_b, uint32_t stride,
                                          int row, int c4, float4 v){
  uint32_t h0 = packbf(v.x, v.y), h1 = packbf(v.z, v.w);
  float rx = v.x - __uint_as_float(h0 << 16);
  float ry = v.y - __uint_as_float(h0 & 0xFFFF0000u);
  float rz = v.z - __uint_as_float(h1 << 16);
  float rw = v.w - __uint_as_float(h1 & 0xFFFF0000u);
  uint32_t l0 = packbf(rx, ry), l1 = packbf(rz, rw);
  uint32_t off = (uint32_t)row*stride + (uint32_t)c4*2;
  sts_v2(hi_b + off, h0, h1);
  sts_v2(lo_b + off, l0, l1);
}

// ---------------- tensor-core GEMM: C(4096x1024) = A @ Wt^T + bias ----------------
#define KSTR 80
#define TILE_BY (128*KSTR)
#define STAGE_BY (4*TILE_BY)
#define SMEM_MMA (2*STAGE_BY)

__global__ __launch_bounds__(256, 1) void gemm_mma(
    const float* __restrict__ A, const float* __restrict__ Wt,
    const float* __restrict__ bias, float* __restrict__ Cmat)
{
  extern __shared__ char smem[];
  uint32_t sb = smem_to_u32(smem);
  int tid = threadIdx.x, lane = tid & 31, wid = tid >> 5;
  int wm = wid & 3, wn = wid >> 2;
  int brow = blockIdx.y * 128, bcol = blockIdx.x * 128;

  float acc[2][8][4];
  #pragma unroll
  for (int i=0;i<2;i++)
    #pragma unroll
    for (int j=0;j<8;j++)
      #pragma unroll
      for (int q=0;q<4;q++) acc[i][j][q]=0.f;

  int lrow = tid >> 3, lkc = tid & 7;
  float4 ra[4], rb[4];
  #pragma unroll
  for (int j=0;j<4;j++){
    int row = lrow + j*32;
    ra[j] = *(const float4*)(A  + (size_t)(brow+row)*Dmod + lkc*4);
    rb[j] = *(const float4*)(Wt + (size_t)(bcol+row)*Dmod + lkc*4);
  }
  #pragma unroll
  for (int j=0;j<4;j++){
    cvt_sts_s(sb,             sb +   TILE_BY, KSTR, lrow + j*32, lkc*4, ra[j]);
    cvt_sts_s(sb + 2*TILE_BY, sb + 3*TILE_BY, KSTR, lrow + j*32, lkc*4, rb[j]);
  }

  for (int c = 0; c < 32; c++){
    __syncthreads();
    uint32_t stg = sb + (uint32_t)(c & 1)*STAGE_BY;
    if (c < 31){
      int k0 = (c+1)*32;
      #pragma unroll
      for (int j=0;j<4;j++){
        int row = lrow + j*32;
        ra[j] = *(const float4*)(A  + (size_t)(brow+row)*Dmod + k0 + lkc*4);
        rb[j] = *(const float4*)(Wt + (size_t)(bcol+row)*Dmod + k0 + lkc*4);
      }
    }
    uint32_t aRow = (uint32_t)(wm*32 + (lane & 15));
    uint32_t aKof = (uint32_t)((lane >> 4) * 16);
    uint32_t bRow = (uint32_t)(wn*64 + (lane & 7) + ((lane >> 4) * 8));
    uint32_t bKof = (uint32_t)(((lane >> 3) & 1) * 16);
    #pragma unroll
    for (int kk = 0; kk < 2; kk++){
      uint32_t kb = (uint32_t)kk*32;
      uint32_t ah[2][4], al[2][4];
      #pragma unroll
      for (int mi=0; mi<2; mi++){
        uint32_t addr = stg + (aRow + mi*16)*KSTR + aKof + kb;
        ldm_x4(addr, ah[mi]);
        ldm_x4(addr + TILE_BY, al[mi]);
      }
      uint32_t bh[4][4], bl[4][4];
      #pragma unroll
      for (int nb=0; nb<4; nb++){
        uint32_t addr = stg + 2*TILE_BY + (bRow + nb*16)*KSTR + bKof + kb;
        ldm_x4(addr, bh[nb]);
        ldm_x4(addr + TILE_BY, bl[nb]);
      }
      #pragma unroll
      for (int mi=0; mi<2; mi++)
        #pragma unroll
        for (int ni=0; ni<8; ni++){
          int nb = ni >> 1, hp = (ni & 1) * 2;
          mma_bf16(acc[mi][ni], ah[mi], bh[nb][hp], bh[nb][hp+1]);
          mma_bf16(acc[mi][ni], ah[mi], bl[nb][hp], bl[nb][hp+1]);
          mma_bf16(acc[mi][ni], al[mi], bh[nb][hp], bh[nb][hp+1]);
        }
    }
    if (c < 31){
      uint32_t nstg = sb + (uint32_t)((c+1) & 1)*STAGE_BY;
      #pragma unroll
      for (int j=0;j<4;j++){
        cvt_sts_s(nstg,             nstg +   TILE_BY, KSTR, lrow + j*32, lkc*4, ra[j]);
        cvt_sts_s(nstg + 2*TILE_BY, nstg + 3*TILE_BY, KSTR, lrow + j*32, lkc*4, rb[j]);
      }
    }
  }

  #pragma unroll
  for (int mi=0; mi<2; mi++){
    int r0 = brow + wm*32 + mi*16 + (lane >> 2);
    #pragma unroll
    for (int ni=0; ni<8; ni++){
      int c0 = bcol + wn*64 + ni*8 + (lane & 3)*2;
      float b0 = bias[c0], b1 = bias[c0+1];
      *(float2*)(Cmat + (size_t)r0*Dmod + c0) =
        make_float2(acc[mi][ni][0] + b0, acc[mi][ni][1] + b1);
      *(float2*)(Cmat + (size_t)(r0+8)*Dmod + c0) =
        make_float2(acc[mi][ni][2] + b0, acc[mi][ni][3] + b1);
    }
  }
}

// ---------------- fused scores + softmax*mask + renorm (per bh, 32-q tile) ----------------
#define ZROW   2064                // 512*4 + 16 pad
#define ZOFF_S 0                   // 32*2064 = 66048
#define ZOFF_CP 66048              // 512*16 = 8192
#define ZOFF_Q 74240               // hi/lo 2*4608 = 9216
#define ZQT    4608
#define ZOFF_K 83456               // hi/lo 2*18432 = 36864
#define ZKT    18432
#define SMEM_ZS 120320

__global__ __launch_bounds__(256, 1) void scores_soft(){
  extern __shared__ char smem[];
  uint32_t sb = smem_to_u32(smem);
  int bh = blockIdx.x, b = bh >> 4, h = bh & 15;
  int q0 = blockIdx.y * 32;
  int tid = threadIdx.x, lane = tid & 31, wid = tid >> 5;
  int wmS = wid & 1, wnS = wid >> 1;
  uint32_t Qb = sb + ZOFF_Q, Kb = sb + ZOFF_K;

  // cp slice -> smem (once per block)
  const float4* cpg = ((const float4*)g_cpq) + (size_t)bh*Lc;
  float4* cps = (float4*)(smem + ZOFF_CP);
  #pragma unroll
  for (int j=0;j<2;j++) cps[tid + j*256] = cpg[tid + j*256];

  // Q tile 32x64 -> bf16 hi/lo
  #pragma unroll
  for (int j=0;j<2;j++){
    int idx = tid + j*256; int row = idx >> 4, c4 = (idx & 15) << 2;
    float4 v = *(const float4*)(g_q + ((size_t)(b*Lc + q0 + row))*Dmod + h*Dkc + c4);
    cvt_sts_s(Qb, Qb + ZQT, 144, row, c4, v);
  }

  // K chunks of 128, single buffer + register prefetch
  float4 st[8];
  #pragma unroll
  for (int j=0;j<8;j++){
    int idx = tid + j*256; int row = idx >> 4, c4 = (idx & 15) << 2;
    st[j] = *(const float4*)(g_k + ((size_t)(b*Lc + row))*Dmod + h*Dkc + c4);
  }
  #pragma unroll
  for (int j=0;j<8;j++){
    int idx = tid + j*256; int row = idx >> 4, c4 = (idx & 15) << 2;
    cvt_sts_s(Kb, Kb + ZKT, 144, row, c4, st[j]);
  }
  for (int kc = 0; kc < 4; kc++){
    __syncthreads();
    if (kc < 3){
      int k0 = (kc+1)*128;
      #pragma unroll
      for (int j=0;j<8;j++){
        int idx = tid + j*256; int row = idx >> 4, c4 = (idx & 15) << 2;
        st[j] = *(const float4*)(g_k + ((size_t)(b*Lc + k0 + row))*Dmod + h*Dkc + c4);
      }
    }
    float acc[4][4];
    #pragma unroll
    for (int i=0;i<4;i++)
      #pragma unroll
      for (int q=0;q<4;q++) acc[i][q] = 0.f;
    uint32_t aR = (uint32_t)(wmS*16 + (lane & 15));
    uint32_t aK = (uint32_t)((lane >> 4) * 16);
    uint32_t bR = (uint32_t)(wnS*32 + (lane & 7) + ((lane >> 4) * 8));
    uint32_t bK = (uint32_t)(((lane >> 3) & 1) * 16);
    #pragma unroll
    for (int ks = 0; ks < 4; ks++){
      uint32_t ko = (uint32_t)ks*32;
      uint32_t ah[4], al[4];
      ldm_x4(Qb + aR*144 + aK + ko, ah);
      ldm_x4(Qb + ZQT + aR*144 + aK + ko, al);
      uint32_t bhh[2][4], bll[2][4];
      #pragma unroll
      for (int nb=0; nb<2; nb++){
        uint32_t ad = Kb + (bR + nb*16)*144 + bK + ko;
        ldm_x4(ad, bhh[nb]);
        ldm_x4(ad + ZKT, bll[nb]);
      }
      #pragma unroll
      for (int ni=0; ni<4; ni++){
        int nb = ni >> 1, hp = (ni & 1)*2;
        mma_bf16(acc[ni], ah, bhh[nb][hp], bhh[nb][hp+1]);
        mma_bf16(acc[ni], ah, bll[nb][hp], bll[nb][hp+1]);
        mma_bf16(acc[ni], al, bhh[nb][hp], bhh[nb][hp+1]);
      }
    }
    #pragma unroll
    for (int ni=0; ni<4; ni++){
      int r0 = wmS*16 + (lane >> 2);
      int col = kc*128 + wnS*32 + ni*8 + (lane & 3)*2;
      *(float2*)(smem + ZOFF_S + (size_t)r0*ZROW + (size_t)col*4) =
        make_float2(acc[ni][0]*0.125f, acc[ni][1]*0.125f);
      *(float2*)(smem + ZOFF_S + (size_t)(r0+8)*ZROW + (size_t)col*4) =
        make_float2(acc[ni][2]*0.125f, acc[ni][3]*0.125f);
    }
    __syncthreads();
    if (kc < 3){
      #pragma unroll
      for (int j=0;j<8;j++){
        int idx = tid + j*256; int row = idx >> 4, c4 = (idx & 15) << 2;
        cvt_sts_s(Kb, Kb + ZKT, 144, row, c4, st[j]);
      }
    }
  }
  __syncthreads();
  // softmax + mask + renorm; write final attn to global
  #pragma unroll
  for (int r=0; r<4; r++){
    int row = wid*4 + r;
    char* srow = smem + ZOFF_S + (size_t)row*ZROW;
    float2 s2[8];
    #pragma unroll
    for (int t=0;t<8;t++) s2[t] = *(float2*)(srow + 8*lane + t*256);
    float mx = -3.0e38f;
    #pragma unroll
    for (int t=0;t<8;t++) mx = fmaxf(mx, fmaxf(s2[t].x, s2[t].y));
    mx = wmax32(mx);
    float es = 0.f;
    #pragma unroll
    for (int t=0;t<8;t++){
      s2[t].x = fexp(s2[t].x - mx); s2[t].y = fexp(s2[t].y - mx);
      es += s2[t].x + s2[t].y;
    }
    es = wsum32(es);
    float inv_se = 1.0f/es;
    float4 cq = cps[q0 + row];
    float ts = 0.f;
    #pragma unroll
    for (int t=0;t<8;t++){
      int k = 2*lane + t*64;
      float4 c0 = cps[k], c1 = cps[k+1];
      float m0 = cq.x*c0.x + cq.y*c0.y + cq.z*c0.z + cq.w*c0.w;
      float m1 = cq.x*c1.x + cq.y*c1.y + cq.z*c1.z + cq.w*c1.w;
      s2[t].x *= inv_se*m0; s2[t].y *= inv_se*m1;
      ts += s2[t].x + s2[t].y;
    }
    ts = wsum32(ts);
    float inv = 1.0f/(ts + 1e-6f);
    float* grow = g_attn + ((size_t)bh*Lc + q0 + row)*Lc;
    #pragma unroll
    for (int t=0;t<8;t++){
      *(float2*)(grow + 2*lane + t*64) = make_float2(s2[t].x*inv, s2[t].y*inv);
    }
  }
}

// ---------------- attn mean over heads ----------------
__global__ void attn_mean_kernel(float* __restrict__ am){
  int idx = blockIdx.x*256 + threadIdx.x;
  int b = idx/(Lc*Lc); int rem = idx - b*(Lc*Lc);
  size_t base = (size_t)b*Hc*Lc*Lc + rem;
  float s=0.f;
  #pragma unroll
  for (int h=0;h<Hc;h++) s += g_attn[base + (size_t)h*Lc*Lc];
  am[idx] = s*(1.0f/(float)Hc);
}

// ---------------- ctx via MMA: ctx = attn @ V ----------------
#define CKSTR 80
#define CA_TILE (128*CKSTR)
#define CB_TILE (64*CKSTR)
#define CSTAGE (2*CA_TILE + 2*CB_TILE)
#define SMEM_CTX (2*CSTAGE)
__global__ __launch_bounds__(256) void ctx_mma(const float* __restrict__ vt){
  extern __shared__ char smem[];
  uint32_t sb = smem_to_u32(smem);
  int bh = blockIdx.x, b = bh >> 4, h = bh & 15;
  int q0 = blockIdx.y << 7;
  int tid = threadIdx.x, lane = tid & 31, wid = tid >> 5;
  int wm = wid & 3, wn = wid >> 2;
  float acc[2][4][4];
  #pragma unroll
  for (int i=0;i<2;i++)
    #pragma unroll
    for (int j=0;j<4;j++)
      #pragma unroll
      for (int q=0;q<4;q++) acc[i][j][q]=0.f;

  const float* abase = g_attn + (size_t)bh*Lc*Lc;
  const float* bbase = vt + (size_t)bh*64*Lc;
  int arow = tid >> 3, ac4 = (tid & 7) << 2;
  float4 ra[4], rb[2];
  #pragma unroll
  for (int j=0;j<4;j++)
    ra[j] = *(const float4*)(abase + (size_t)(q0 + arow + j*32)*Lc + ac4);
  #pragma unroll
  for (int j=0;j<2;j++){
    int idx = tid + j*256; int row = idx >> 3; int c4 = (idx & 7) << 2;
    rb[j] = *(const float4*)(bbase + (size_t)row*Lc + c4);
  }
  #pragma unroll
  for (int j=0;j<4;j++)
    cvt_sts_s(sb, sb + CA_TILE, CKSTR, arow + j*32, ac4, ra[j]);
  #pragma unroll
  for (int j=0;j<2;j++){
    int idx = tid + j*256; int row = idx >> 3; int c4 = (idx & 7) << 2;
    cvt_sts_s(sb + 2*CA_TILE, sb + 2*CA_TILE + CB_TILE, CKSTR, row, c4, rb[j]);
  }

  for (int c = 0; c < 16; c++){
    __syncthreads();
    uint32_t stg = sb + (uint32_t)(c & 1)*CSTAGE;
    if (c < 15){
      int k0 = (c+1)*32;
      #pragma unroll
      for (int j=0;j<4;j++)
        ra[j] = *(const float4*)(abase + (size_t)(q0 + arow + j*32)*Lc + k0 + ac4);
      #pragma unroll
      for (int j=0;j<2;j++){
        int idx = tid + j*256; int row = idx >> 3; int c4 = (idx & 7) << 2;
        rb[j] = *(const float4*)(bbase + (size_t)row*Lc + k0 + c4);
      }
    }
    uint32_t aRow = (uint32_t)(wm*32 + (lane & 15));
    uint32_t aKof = (uint32_t)((lane >> 4) * 16);
    uint32_t bRow = (uint32_t)(wn*32 + (lane & 7) + ((lane >> 4) * 8));
    uint32_t bKof = (uint32_t)(((lane >> 3) & 1) * 16);
    #pragma unroll
    for (int kk = 0; kk < 2; kk++){
      uint32_t kb = (uint32_t)kk*32;
      uint32_t ah[2][4], al[2][4];
      #pragma unroll
      for (int mi=0; mi<2; mi++){
        uint32_t addr = stg + (aRow + mi*16)*CKSTR + aKof + kb;
        ldm_x4(addr, ah[mi]);
        ldm_x4(addr + CA_TILE, al[mi]);
      }
      uint32_t bhh[2][4], bll[2][4];
      #pragma unroll
      for (int nb=0; nb<2; nb++){
        uint32_t addr = stg + 2*CA_TILE + (bRow + nb*16)*CKSTR + bKof + kb;
        ldm_x4(addr, bhh[nb]);
        ldm_x4(addr + CB_TILE, bll[nb]);
      }
      #pragma unroll
      for (int mi=0; mi<2; mi++)
        #pragma unroll
        for (int ni=0; ni<4; ni++){
          int nb = ni >> 1, hp = (ni & 1) * 2;
          mma_bf16(acc[mi][ni], ah[mi], bhh[nb][hp], bhh[nb][hp+1]);
          mma_bf16(acc[mi][ni], ah[mi], bll[nb][hp], bll[nb][hp+1]);
          mma_bf16(acc[mi][ni], al[mi], bhh[nb][hp], bhh[nb][hp+1]);
        }
    }
    if (c < 15){
      uint32_t nstg = sb + (uint32_t)((c+1) & 1)*CSTAGE;
      #pragma unroll
      for (int j=0;j<4;j++)
        cvt_sts_s(nstg, nstg + CA_TILE, CKSTR, arow + j*32, ac4, ra[j]);
      #pragma unroll
      for (int j=0;j<2;j++){
        int idx = tid + j*256; int row = idx >> 3; int c4 = (idx & 7) << 2;
        cvt_sts_s(nstg + 2*CA_TILE, nstg + 2*CA_TILE + CB_TILE, CKSTR, row, c4, rb[j]);
      }
    }
  }
  #pragma unroll
  for (int mi=0; mi<2; mi++){
    int r0 = b*Lc + q0 + wm*32 + mi*16 + (lane >> 2);
    #pragma unroll
    for (int ni=0; ni<4; ni++){
      int c0 = h*Dkc + wn*32 + ni*8 + (lane & 3)*2;
      *(float2*)(g_ctx + (size_t)r0*Dmod + c0) =
        make_float2(acc[mi][ni][0], acc[mi][ni][1]);
      *(float2*)(g_ctx + (size_t)(r0+8)*Dmod + c0) =
        make_float2(acc[mi][ni][2], acc[mi][ni][3]);
    }
  }
}

// W[k][n] -> Wt[n][k]
__global__ void transpose_kernel(const float* __restrict__ W, float* __restrict__ Wt){
  __shared__ float t[32][33];
  int n0 = blockIdx.x*32, k0 = blockIdx.y*32;
  int tx = threadIdx.x, ty = threadIdx.y;
  for (int i = ty; i < 32; i += 8) t[i][tx] = W[(size_t)(k0+i)*Dmod + n0 + tx];
  __syncthreads();
  for (int i = ty; i < 32; i += 8) Wt[(size_t)(n0+i)*Dmod + k0 + tx] = t[tx][i];
}
__global__ void transpose_v(const float* __restrict__ v, float* __restrict__ vt){
  __shared__ float t[32][33];
  int bh = blockIdx.x, b = bh >> 4, h = bh & 15;
  int l0 = blockIdx.y*32, d0 = blockIdx.z*32;
  int tx = threadIdx.x, ty = threadIdx.y;
  for (int i = ty; i < 32; i += 8)
    t[i][tx] = v[(size_t)(b*Lc + l0 + i)*Dmod + h*Dkc + d0 + tx];
  __syncthreads();
  for (int i = ty; i < 32; i += 8)
    vt[((size_t)bh*64 + d0 + i)*Lc + l0 + tx] = t[tx][i];
}

// ---------------- reductions ----------------
template<int NT>
__device__ __forceinline__ float blockSum(float v, float* red){
  int t = threadIdx.x; red[t] = v; __syncthreads();
  #pragma unroll
  for (int s = NT/2; s > 0; s >>= 1){ if (t < s) red[t] += red[t+s]; __syncthreads(); }
  float r = red[0]; __syncthreads(); return r;
}
template<int NT>
__device__ __forceinline__ float blockMax(float v, float* red){
  int t = threadIdx.x; red[t] = v; __syncthreads();
  #pragma unroll
  for (int s = NT/2; s > 0; s >>= 1){ if (t < s) red[t] = fmaxf(red[t], red[t+s]); __syncthreads(); }
  float r = red[0]; __syncthreads(); return r;
}
__device__ __forceinline__ void atomicMaxF(float* a, float v){
  if (v >= 0.f) atomicMax((int*)a, __float_as_int(v));
  else atomicMin((unsigned int*)a, (unsigned int)__float_as_int(v));
}

__global__ void zero_kernel(float* scal){
  int t = threadIdx.x;
  if (t < 24) scal[t] = 0.f;
  if (t == 0) g_gmax = -3.0e38f;
}

__global__ void gemm16_kernel(const float* __restrict__ A, const float* __restrict__ W,
                              const float* __restrict__ bias, float* __restrict__ out){
  int g = blockIdx.x*256 + threadIdx.x;
  int row = g>>4, h = g&15;
  const float* a = A + (size_t)row*Dmod;
  float acc = 0.f;
  for (int k=0;k<Dmod;k+=4){
    float4 av = *(const float4*)(a+k);
    acc += av.x*W[k*16+h] + av.y*W[(k+1)*16+h] + av.z*W[(k+2)*16+h] + av.w*W[(k+3)*16+h];
  }
  out[g] = acc + bias[h];
}

template<bool HEAD>
__global__ __launch_bounds__(512) void cluster_kernel(
    const float* __restrict__ X, const float* __restrict__ alvArr,
    const float* __restrict__ mu, const float* __restrict__ logvar,
    const float* __restrict__ logprior, float* __restrict__ cpOut,
    float* __restrict__ lpdfOut, float* __restrict__ klOut)
{
  int bh = blockIdx.x; int b = bh/Hc, h = bh%Hc;
  int l = threadIdx.x;
  __shared__ float mu_s[Cc][Dkc], iv_s[Cc][Dkc];
  __shared__ float lvs[Cc], ivs[Cc], lp_s[Cc];
  __shared__ float red[Lc];
  const float* mup = mu + (HEAD?0:h)*Cc*Dkc;
  const float* lvp = logvar + (HEAD?0:h)*Cc*Dkc;
  for (int i=l;i<Cc*Dkc;i+=blockDim.x){ mu_s[i/Dkc][i%Dkc]=mup[i]; iv_s[i/Dkc][i%Dkc]=expf(-lvp[i]); }
  __syncthreads();
  if (l < Cc){
    float ls=0.f, is=0.f;
    for (int d=0;d<Dkc;d++){ ls+=lvp[l*Dkc+d]; is+=iv_s[l][d]; }
    lvs[l]=ls; ivs[l]=is;
  }
  if (l == 0){
    const float* pr = logprior + (HEAD?0:h)*Cc;
    float m=pr[0]; for(int c=1;c<Cc;c++) m=fmaxf(m,pr[c]);
    float s=0.f; for(int c=0;c<Cc;c++) s+=expf(pr[c]-m);
    float lse=m+logf(s);
    for(int c=0;c<Cc;c++) lp_s[c]=pr[c]-lse;
  }
  __syncthreads();
  const float* z = X + ((size_t)(b*Lc+l))*Dmod + h*Dkc;
  float mse[Cc] = {0.f,0.f,0.f,0.f};
  #pragma unroll
  for (int d4=0; d4<Dkc/4; d4++){
    float4 zv = *(const float4*)(z + d4*4);
    #pragma unroll
    for (int c=0;c<Cc;c++){
      float t0=zv.x-mu_s[c][d4*4], t1=zv.y-mu_s[c][d4*4+1];
      float t2=zv.z-mu_s[c][d4*4+2], t3=zv.w-mu_s[c][d4*4+3];
      mse[c]+= t0*t0*iv_s[c][d4*4]+t1*t1*iv_s[c][d4*4+1]+t2*t2*iv_s[c][d4*4+2]+t3*t3*iv_s[c][d4*4+3];
    }
  }
  const float CPI = 64.0f*3.14159265358979323846f;
  float lpdf[Cc]; float mx=-3.0e38f;
  #pragma unroll
  for (int c=0;c<Cc;c++){ lpdf[c] = -0.5f*mse[c] - 0.5f*lvs[c] - CPI + lp_s[c]; mx=fmaxf(mx,lpdf[c]); }
  float se=0.f;
  #pragma unroll
  for (int c=0;c<Cc;c++) se += expf(lpdf[c]-mx);
  float lse = mx + logf(se);
  float kl=0.f; float cp[Cc];
  size_t ob = ((size_t)bh*Lc + l)*Cc;
  #pragma unroll
  for (int c=0;c<Cc;c++){
    float lq = lpdf[c]-lse;
    cp[c] = expf(lq);
    kl += expf(lp_s[c])*(lp_s[c]-lq);
    cpOut[ob+c] = cp[c];
    if (HEAD) lpdfOut[ob+c] = lpdf[c];
  }
  float alv = alvArr[(b*Lc+l)*Hc+h];
  float avar = expf(alv);
  float k2=0.f;
  #pragma unroll
  for (int c=0;c<Cc;c++) k2 += cp[c]*(mse[c] + avar*ivs[c] + lvs[c]);
  kl += 0.5f*k2 - 0.5f*(float)Dkc*(1.0f+alv);
  float tot = blockSum<512>(kl, red);
  if (l==0) atomicAdd(&klOut[b], tot*(1.0f/((float)Hc*Lc)));
  if (HEAD){
    float bm = blockMax<512>(mx, red);
    if (l==0) atomicMaxF(&g_gmax, bm);
  }
}

// ---------------- div via 4x4 Gram ----------------
__global__ __launch_bounds__(512) void div_fast(const float4* __restrict__ cp, float* __restrict__ divOut){
  int bh = blockIdx.x; int b = bh/Hc;
  __shared__ float red[512];
  float4 p = cp[(size_t)bh*Lc + threadIdx.x];
  float g = p.x*p.x + p.y*p.y + p.z*p.z + p.w*p.w;
  float m[10] = {p.x*p.x, p.x*p.y, p.x*p.z, p.x*p.w,
                 p.y*p.y, p.y*p.z, p.y*p.w,
                 p.z*p.z, p.z*p.w, p.w*p.w};
  float dterm = 1.25f*(g-1.0f)*(g-1.0f) - 0.75f*g*g;
  float Ms[10];
  #pragma unroll
  for (int i=0;i<10;i++) Ms[i] = blockSum<512>(m[i], red);
  float dsum = blockSum<512>(dterm, red);
  if (threadIdx.x == 0){
    float frob = Ms[0]*Ms[0] + Ms[4]*Ms[4] + Ms[7]*Ms[7] + Ms[9]*Ms[9]
      + 2.0f*(Ms[1]*Ms[1] + Ms[2]*Ms[2] + Ms[3]*Ms[3] + Ms[5]*Ms[5] + Ms[6]*Ms[6] + Ms[8]*Ms[8]);
    atomicAdd(&divOut[b], (0.75f*frob + dsum) * (1.0f/((float)Hc*Lc*Lc)));
  }
}

__global__ __launch_bounds__(512) void pdf_wsum_kernel(){
  int bh=blockIdx.x; int l=threadIdx.x;
  __shared__ float red[512];
  float gm = g_gmax;
  int base = (bh*Lc+l)*Cc;
  float p=0.f;
  #pragma unroll
  for (int c=0;c<Cc;c++) p += fexp(g_lpdf[base+c]-gm);
  g_pdf[bh*Lc+l]=p;
  #pragma unroll
  for (int c=0;c<Cc;c++){
    float s = blockSum<512>(g_cph[base+c]*p, red);
    if (l==0) g_wsum[bh*Cc+c]=s;
  }
}

__global__ __launch_bounds__(512) void mi_kernel(float* __restrict__ miOut){
  int wid = threadIdx.x >> 5, lane = threadIdx.x & 31;
  int bl = blockIdx.x*16 + wid;
  int b = bl >> 9, l = bl & 511;
  float cpv[Cc]={0,0,0,0}, mp[Cc]={0,0,0,0};
  if (lane < Hc){
    int base = ((b*Hc+lane)*Lc+l)*Cc;
    float pd = g_pdf[(b*Hc+lane)*Lc+l];
    #pragma unroll
    for (int c=0;c<Cc;c++){
      cpv[c]=g_cph[base+c];
      mp[c]=cpv[c]*pd/fmaxf(g_wsum[(b*Hc+lane)*Cc+c],1e-6f);
    }
  }
  float acc=0.f;
  for (int j=0;j<Hc;j++){
    float c0=__shfl_sync(0xffffffffu,cpv[0],j);
    float c1=__shfl_sync(0xffffffffu,cpv[1],j);
    float c2=__shfl_sync(0xffffffffu,cpv[2],j);
    float c3=__shfl_sync(0xffffffffu,cpv[3],j);
    if (lane<Hc && lane!=j){
      float p = fminf(mp[0]*c0+mp[1]*c1+mp[2]*c2+mp[3]*c3, 1.0f);
      acc += logf(1.0f-p+1e-6f);
    }
  }
  #pragma unroll
  for (int o=16;o>0;o>>=1) acc += __shfl_down_sync(0xffffffffu,acc,o);
  if (lane==0) atomicAdd(&miOut[b], acc*(-10.0f/((float)Lc*Hc*Hc)));
}

__global__ __launch_bounds__(512) void diag_kernel(float* __restrict__ miOut){
  int bh=blockIdx.x; int b=bh>>4;
  __shared__ float4 cps[Lc];
  __shared__ float red[512];
  for (int i=threadIdx.x;i<Lc;i+=512) cps[i]=((const float4*)g_cph)[(size_t)bh*Lc+i];
  __syncthreads();
  int q=threadIdx.x;
  float4 a=cps[q];
  float s=0.f, dq=0.f;
  for (int k=0;k<Lc;k++){
    float4 c=cps[k];
    float g=a.x*c.x+a.y*c.y+a.z*c.z+a.w*c.w;
    if (k==q) dq=g;
    s += fexp(g);
  }
  float tot = blockSum<512>(dq-logf(s), red);
  if (threadIdx.x==0) atomicAdd(&miOut[b], -tot/((float)Hc*Lc));
}

extern "C" void kernel_launch(void* const* d_in, const int* in_sizes, int n_in,
                              void* d_out, int out_size){
  const float *query=(const float*)d_in[0], *key=(const float*)d_in[1], *value=(const float*)d_in[2];
  const float *Wq=(const float*)d_in[3], *bq=(const float*)d_in[4];
  const float *Wk=(const float*)d_in[5], *bk=(const float*)d_in[6];
  const float *Wv=(const float*)d_in[7], *bv=(const float*)d_in[8];
  const float *Wo=(const float*)d_in[9], *bo=(const float*)d_in[10];
  const float *Wsem=(const float*)d_in[11], *bsem=(const float*)d_in[12];
  const float *Whead=(const float*)d_in[13], *bhead=(const float*)d_in[14];
  const float *tmu=(const float*)d_in[15], *tlv=(const float*)d_in[16], *tlp=(const float*)d_in[17];
  const float *hmu=(const float*)d_in[18], *hlv=(const float*)d_in[19], *hlp=(const float*)d_in[20];
  float* out = (float*)d_out;
  float* am  = out + OUT_N;
  float* kl  = out + KL_OFF;
  float* dv  = out + KL_OFF + 8;
  float* mi  = out + KL_OFF + 16;

  float *pq,*pk,*pv,*pvt,*pctx,*pwt,*pwt2,*pwt3,*pwt4,*palv,*palvh,*pcpq,*pcph,*plpdf;
  cudaGetSymbolAddress((void**)&pq, g_q);
  cudaGetSymbolAddress((void**)&pk, g_k);
  cudaGetSymbolAddress((void**)&pv, g_v);
  cudaGetSymbolAddress((void**)&pvt, g_vt);
  cudaGetSymbolAddress((void**)&pctx, g_ctx);
  cudaGetSymbolAddress((void**)&pwt, g_wt);
  cudaGetSymbolAddress((void**)&pwt2, g_wt2);
  cudaGetSymbolAddress((void**)&pwt3, g_wt3);
  cudaGetSymbolAddress((void**)&pwt4, g_wt4);
  cudaGetSymbolAddress((void**)&palv, g_alv);
  cudaGetSymbolAddress((void**)&palvh, g_alvh);
  cudaGetSymbolAddress((void**)&pcpq, g_cpq);
  cudaGetSymbolAddress((void**)&pcph, g_cph);
  cudaGetSymbolAddress((void**)&plpdf, g_lpdf);

  cudaFuncSetAttribute(gemm_mma, cudaFuncAttributeMaxDynamicSharedMemorySize, SMEM_MMA);
  cudaFuncSetAttribute(scores_soft, cudaFuncAttributeMaxDynamicSharedMemorySize, SMEM_ZS);
  cudaFuncSetAttribute(ctx_mma, cudaFuncAttributeMaxDynamicSharedMemorySize, SMEM_CTX);

  int M = Bc*Lc;
  dim3 gt(32, 32), bt(32, 8);
  dim3 gg(Dmod/128, M/128);

  zero_kernel<<<1, 32>>>(kl);
  transpose_kernel<<<gt, bt>>>(Wq, pwt);
  transpose_kernel<<<gt, bt>>>(Wk, pwt2);
  transpose_kernel<<<gt, bt>>>(Wv, pwt3);
  transpose_kernel<<<gt, bt>>>(Wo, pwt4);
  gemm_mma<<<gg, 256, SMEM_MMA>>>(query, pwt, bq, pq);
  gemm_mma<<<gg, 256, SMEM_MMA>>>(key, pwt2, bk, pk);
  gemm_mma<<<gg, 256, SMEM_MMA>>>(value, pwt3, bv, pv);
  transpose_v<<<dim3(Bc*Hc, Lc/32, Dkc/32), bt>>>(pv, pvt);
  gemm16_kernel<<<M*16/256, 256>>>(pq, Wsem, bsem, palv);
  cluster_kernel<false><<<Bc*Hc, 512>>>(pq, palv, tmu, tlv, tlp, pcpq, nullptr, kl);
  div_fast<<<Bc*Hc, 512>>>((const float4*)pcpq, dv);
  scores_soft<<<dim3(Bc*Hc, Lc/32), 256, SMEM_ZS>>>();
  attn_mean_kernel<<<AM_N/256, 256>>>(am);
  ctx_mma<<<dim3(Bc*Hc, Lc/128), 256, SMEM_CTX>>>(pvt);
  gemm16_kernel<<<M*16/256, 256>>>(pctx, Whead, bhead, palvh);
  cluster_kernel<true><<<Bc*Hc, 512>>>(pctx, palvh, hmu, hlv, hlp, pcph, plpdf, kl);
  div_fast<<<Bc*Hc, 512>>>((const float4*)pcph, dv);
  pdf_wsum_kernel<<<Bc*Hc, 512>>>();
  mi_kernel<<<Bc*Lc/16, 512>>>(mi);
  diag_kernel<<<Bc*Hc, 512>>>(mi);
  gemm_mma<<<gg, 256, SMEM_MMA>>>(pctx, pwt4, bo, out);
}

// round 15
// speedup vs baseline: 1.0256x; 1.0256x over previous
#include <cuda_runtime.h>
#include <cuda_bf16.h>
#include <cstdint>
#include <math.h>

#define Bc 8
#define Lc 512
#define Dmod 1024
#define Hc 16
#define Cc 4
#define Dkc 64
#define OUT_N  (Bc*Lc*Dmod)
#define AM_N   (Bc*Lc*Lc)
#define KL_OFF (OUT_N + AM_N)

__device__ float g_q[OUT_N];
__device__ float g_k[OUT_N];
__device__ float g_v[OUT_N];
__device__ float g_vt[OUT_N];
__device__ float g_ctx[OUT_N];
__device__ float g_wt[Dmod*Dmod];
__device__ float g_wt2[Dmod*Dmod];
__device__ float g_wt3[Dmod*Dmod];
__device__ float g_wt4[Dmod*Dmod];
__device__ float g_alv[Bc*Lc*Hc];
__device__ float g_alvh[Bc*Lc*Hc];
__device__ float g_cpq[Bc*Hc*Lc*Cc];
__device__ float g_cph[Bc*Hc*Lc*Cc];
__device__ float g_lpdf[Bc*Hc*Lc*Cc];
__device__ float g_pdf[Bc*Hc*Lc];
__device__ float g_wsum[Bc*Hc*Cc];
__device__ float g_attn[(size_t)Bc*Hc*Lc*Lc];
__device__ float g_gmax;

// ---------------- portable PTX helpers (sm_80+) ----------------
__device__ __forceinline__ uint32_t smem_to_u32(const void* p) {
  uint32_t a;
  asm("{ .reg .u64 t; cvta.to.shared.u64 t, %1; cvt.u32.u64 %0, t; }" : "=r"(a) : "l"(p));
  return a;
}
__device__ __forceinline__ void ldm_x4(uint32_t addr, uint32_t r[4]){
  asm volatile("ldmatrix.sync.aligned.m8n8.x4.shared.b16 {%0,%1,%2,%3}, [%4];"
    : "=r"(r[0]),"=r"(r[1]),"=r"(r[2]),"=r"(r[3]) : "r"(addr));
}
__device__ __forceinline__ void mma_bf16(float c[4], const uint32_t a[4], uint32_t b0, uint32_t b1){
  asm volatile("mma.sync.aligned.m16n8k16.row.col.f32.bf16.bf16.f32 "
    "{%0,%1,%2,%3}, {%4,%5,%6,%7}, {%8,%9}, {%0,%1,%2,%3};"
    : "+f"(c[0]),"+f"(c[1]),"+f"(c[2]),"+f"(c[3])
    : "r"(a[0]),"r"(a[1]),"r"(a[2]),"r"(a[3]), "r"(b0),"r"(b1));
}
__device__ __forceinline__ uint32_t packbf(float a, float b){ // lo16=a, hi16=b
  uint32_t r; asm("cvt.rn.bf16x2.f32 %0, %1, %2;" : "=r"(r) : "f"(b), "f"(a)); return r;
}
__device__ __forceinline__ void sts_v2(uint32_t a, uint32_t x, uint32_t y){
  asm volatile("st.shared.v2.b32 [%0], {%1, %2};" :: "r"(a), "r"(x), "r"(y) : "memory");
}
__device__ __forceinline__ float fexp(float x){
  x = fmaxf(x, -87.0f);
  float y = x * 1.4426950408889634f;
  float n = rintf(y);
  float f = (y - n) * 0.6931471805599453f;
  float p = 0.0013888889f;
  p = fmaf(p, f, 0.0083333333f);
  p = fmaf(p, f, 0.0416666667f);
  p = fmaf(p, f, 0.1666666667f);
  p = fmaf(p, f, 0.5f);
  p = fmaf(p, f, 1.0f);
  p = fmaf(p, f, 1.0f);
  int e = (int)n;
  return p * __int_as_float((e + 127) << 23);
}
__device__ __forceinline__ float wsum32(float v){
  #pragma unroll
  for (int o=16;o>0;o>>=1) v += __shfl_xor_sync(0xffffffffu, v, o);
  return v;
}
__device__ __forceinline__ float wmax32(float v){
  #pragma unroll
  for (int o=16;o>0;o>>=1) v = fmaxf(v, __shfl_xor_sync(0xffffffffu, v, o));
  return v;
}
__device__ __forceinline__ void cvt_sts_s(uint32_t hi_b, uint32_t lo_b, uint32_t stride,
                                          int row, int c4, float4 v){
  uint32_t h0 = packbf(v.x, v.y), h1 = packbf(v.z, v.w);
  float rx = v.x - __uint_as_float(h0 << 16);
  float ry = v.y - __uint_as_float(h0 & 0xFFFF0000u);
  float rz = v.z - __uint_as_float(h1 << 16);
  float rw = v.w - __uint_as_float(h1 & 0xFFFF0000u);
  uint32_t l0 = packbf(rx, ry), l1 = packbf(rz, rw);
  uint32_t off = (uint32_t)row*stride + (uint32_t)c4*2;
  sts_v2(hi_b + off, h0, h1);
  sts_v2(lo_b + off, l0, l1);
}

// ---------------- tensor-core GEMM: C(4096x1024) = A @ Wt^T + bias ----------------
#define KSTR 80
#define TILE_BY (128*KSTR)
#define STAGE_BY (4*TILE_BY)
#define SMEM_MMA (2*STAGE_BY)

__global__ __launch_bounds__(256, 1) void gemm_mma(
    const float* __restrict__ A, const float* __restrict__ Wt,
    const float* __restrict__ bias, float* __restrict__ Cmat)
{
  extern __shared__ char smem[];
  uint32_t sb = smem_to_u32(smem);
  int tid = threadIdx.x, lane = tid & 31, wid = tid >> 5;
  int wm = wid & 3, wn = wid >> 2;
  int brow = blockIdx.y * 128, bcol = blockIdx.x * 128;

  float acc[2][8][4];
  #pragma unroll
  for (int i=0;i<2;i++)
    #pragma unroll
    for (int j=0;j<8;j++)
      #pragma unroll
      for (int q=0;q<4;q++) acc[i][j][q]=0.f;

  int lrow = tid >> 3, lkc = tid & 7;
  float4 ra[4], rb[4];
  #pragma unroll
  for (int j=0;j<4;j++){
    int row = lrow + j*32;
    ra[j] = *(const float4*)(A  + (size_t)(brow+row)*Dmod + lkc*4);
    rb[j] = *(const float4*)(Wt + (size_t)(bcol+row)*Dmod + lkc*4);
  }
  #pragma unroll
  for (int j=0;j<4;j++){
    cvt_sts_s(sb,             sb +   TILE_BY, KSTR, lrow + j*32, lkc*4, ra[j]);
    cvt_sts_s(sb + 2*TILE_BY, sb + 3*TILE_BY, KSTR, lrow + j*32, lkc*4, rb[j]);
  }

  for (int c = 0; c < 32; c++){
    __syncthreads();
    uint32_t stg = sb + (uint32_t)(c & 1)*STAGE_BY;
    if (c < 31){
      int k0 = (c+1)*32;
      #pragma unroll
      for (int j=0;j<4;j++){
        int row = lrow + j*32;
        ra[j] = *(const float4*)(A  + (size_t)(brow+row)*Dmod + k0 + lkc*4);
        rb[j] = *(const float4*)(Wt + (size_t)(bcol+row)*Dmod + k0 + lkc*4);
      }
    }
    uint32_t aRow = (uint32_t)(wm*32 + (lane & 15));
    uint32_t aKof = (uint32_t)((lane >> 4) * 16);
    uint32_t bRow = (uint32_t)(wn*64 + (lane & 7) + ((lane >> 4) * 8));
    uint32_t bKof = (uint32_t)(((lane >> 3) & 1) * 16);
    #pragma unroll
    for (int kk = 0; kk < 2; kk++){
      uint32_t kb = (uint32_t)kk*32;
      uint32_t ah[2][4], al[2][4];
      #pragma unroll
      for (int mi=0; mi<2; mi++){
        uint32_t addr = stg + (aRow + mi*16)*KSTR + aKof + kb;
        ldm_x4(addr, ah[mi]);
        ldm_x4(addr + TILE_BY, al[mi]);
      }
      uint32_t bh[4][4], bl[4][4];
      #pragma unroll
      for (int nb=0; nb<4; nb++){
        uint32_t addr = stg + 2*TILE_BY + (bRow + nb*16)*KSTR + bKof + kb;
        ldm_x4(addr, bh[nb]);
        ldm_x4(addr + TILE_BY, bl[nb]);
      }
      #pragma unroll
      for (int mi=0; mi<2; mi++)
        #pragma unroll
        for (int ni=0; ni<8; ni++){
          int nb = ni >> 1, hp = (ni & 1) * 2;
          mma_bf16(acc[mi][ni], ah[mi], bh[nb][hp], bh[nb][hp+1]);
          mma_bf16(acc[mi][ni], ah[mi], bl[nb][hp], bl[nb][hp+1]);
          mma_bf16(acc[mi][ni], al[mi], bh[nb][hp], bh[nb][hp+1]);
        }
    }
    if (c < 31){
      uint32_t nstg = sb + (uint32_t)((c+1) & 1)*STAGE_BY;
      #pragma unroll
      for (int j=0;j<4;j++){
        cvt_sts_s(nstg,             nstg +   TILE_BY, KSTR, lrow + j*32, lkc*4, ra[j]);
        cvt_sts_s(nstg + 2*TILE_BY, nstg + 3*TILE_BY, KSTR, lrow + j*32, lkc*4, rb[j]);
      }
    }
  }

  #pragma unroll
  for (int mi=0; mi<2; mi++){
    int r0 = brow + wm*32 + mi*16 + (lane >> 2);
    #pragma unroll
    for (int ni=0; ni<8; ni++){
      int c0 = bcol + wn*64 + ni*8 + (lane & 3)*2;
      float b0 = bias[c0], b1 = bias[c0+1];
      *(float2*)(Cmat + (size_t)r0*Dmod + c0) =
        make_float2(acc[mi][ni][0] + b0, acc[mi][ni][1] + b1);
      *(float2*)(Cmat + (size_t)(r0+8)*Dmod + c0) =
        make_float2(acc[mi][ni][2] + b0, acc[mi][ni][3] + b1);
    }
  }
}

// ---------------- scores via MMA: S = Z K^T / 8 ----------------
#define SKSTR 144
#define STILE_B (128*SKSTR)
#define SMEM_SC (4*STILE_B)
__global__ __launch_bounds__(256) void scores_mma(){
  extern __shared__ char smem[];
  uint32_t sb = smem_to_u32(smem);
  int bh = blockIdx.x, b = bh >> 4, h = bh & 15;
  int q0 = blockIdx.y << 7, k0 = blockIdx.z << 7;
  int tid = threadIdx.x, lane = tid & 31, wid = tid >> 5;
  int wm = wid & 3, wn = wid >> 2;
  #pragma unroll
  for (int j=0;j<8;j++){
    int idx = tid + j*256; int row = idx >> 4; int c4 = (idx & 15) << 2;
    float4 v = *(const float4*)(g_q + ((size_t)(b*Lc + q0 + row))*Dmod + h*Dkc + c4);
    cvt_sts_s(sb, sb + STILE_B, SKSTR, row, c4, v);
    float4 w = *(const float4*)(g_k + ((size_t)(b*Lc + k0 + row))*Dmod + h*Dkc + c4);
    cvt_sts_s(sb + 2*STILE_B, sb + 3*STILE_B, SKSTR, row, c4, w);
  }
  __syncthreads();
  float acc[2][8][4];
  #pragma unroll
  for (int i=0;i<2;i++)
    #pragma unroll
    for (int j=0;j<8;j++)
      #pragma unroll
      for (int q=0;q<4;q++) acc[i][j][q]=0.f;
  uint32_t aRow = (uint32_t)(wm*32 + (lane & 15));
  uint32_t aKof = (uint32_t)((lane >> 4) * 16);
  uint32_t bRow = (uint32_t)(wn*64 + (lane & 7) + ((lane >> 4) * 8));
  uint32_t bKof = (uint32_t)(((lane >> 3) & 1) * 16);
  #pragma unroll
  for (int kk = 0; kk < 4; kk++){
    uint32_t kb = (uint32_t)kk*32;
    uint32_t ah[2][4], al[2][4];
    #pragma unroll
    for (int mi=0; mi<2; mi++){
      uint32_t addr = sb + (aRow + mi*16)*SKSTR + aKof + kb;
      ldm_x4(addr, ah[mi]);
      ldm_x4(addr + STILE_B, al[mi]);
    }
    uint32_t bhh[4][4], bll[4][4];
    #pragma unroll
    for (int nb=0; nb<4; nb++){
      uint32_t addr = sb + 2*STILE_B + (bRow + nb*16)*SKSTR + bKof + kb;
      ldm_x4(addr, bhh[nb]);
      ldm_x4(addr + STILE_B, bll[nb]);
    }
    #pragma unroll
    for (int mi=0; mi<2; mi++)
      #pragma unroll
      for (int ni=0; ni<8; ni++){
        int nb = ni >> 1, hp = (ni & 1) * 2;
        mma_bf16(acc[mi][ni], ah[mi], bhh[nb][hp], bhh[nb][hp+1]);
        mma_bf16(acc[mi][ni], ah[mi], bll[nb][hp], bll[nb][hp+1]);
        mma_bf16(acc[mi][ni], al[mi], bhh[nb][hp], bhh[nb][hp+1]);
      }
  }
  #pragma unroll
  for (int mi=0; mi<2; mi++){
    int r0 = q0 + wm*32 + mi*16 + (lane >> 2);
    #pragma unroll
    for (int ni=0; ni<8; ni++){
      int c0 = k0 + wn*64 + ni*8 + (lane & 3)*2;
      *(float2*)(g_attn + ((size_t)bh*Lc + r0)*Lc + c0) =
        make_float2(acc[mi][ni][0]*0.125f, acc[mi][ni][1]*0.125f);
      *(float2*)(g_attn + ((size_t)bh*Lc + r0 + 8)*Lc + c0) =
        make_float2(acc[mi][ni][2]*0.125f, acc[mi][ni][3]*0.125f);
    }
  }
}

// ---------------- ctx via MMA: ctx = attn @ V ----------------
#define CKSTR 80
#define CA_TILE (128*CKSTR)
#define CB_TILE (64*CKSTR)
#define CSTAGE (2*CA_TILE + 2*CB_TILE)
#define SMEM_CTX (2*CSTAGE)
__global__ __launch_bounds__(256) void ctx_mma(const float* __restrict__ vt){
  extern __shared__ char smem[];
  uint32_t sb = smem_to_u32(smem);
  int bh = blockIdx.x, b = bh >> 4, h = bh & 15;
  int q0 = blockIdx.y << 7;
  int tid = threadIdx.x, lane = tid & 31, wid = tid >> 5;
  int wm = wid & 3, wn = wid >> 2;
  float acc[2][4][4];
  #pragma unroll
  for (int i=0;i<2;i++)
    #pragma unroll
    for (int j=0;j<4;j++)
      #pragma unroll
      for (int q=0;q<4;q++) acc[i][j][q]=0.f;

  const float* abase = g_attn + (size_t)bh*Lc*Lc;
  const float* bbase = vt + (size_t)bh*64*Lc;
  int arow = tid >> 3, ac4 = (tid & 7) << 2;
  float4 ra[4], rb[2];
  #pragma unroll
  for (int j=0;j<4;j++)
    ra[j] = *(const float4*)(abase + (size_t)(q0 + arow + j*32)*Lc + ac4);
  #pragma unroll
  for (int j=0;j<2;j++){
    int idx = tid + j*256; int row = idx >> 3; int c4 = (idx & 7) << 2;
    rb[j] = *(const float4*)(bbase + (size_t)row*Lc + c4);
  }
  #pragma unroll
  for (int j=0;j<4;j++)
    cvt_sts_s(sb, sb + CA_TILE, CKSTR, arow + j*32, ac4, ra[j]);
  #pragma unroll
  for (int j=0;j<2;j++){
    int idx = tid + j*256; int row = idx >> 3; int c4 = (idx & 7) << 2;
    cvt_sts_s(sb + 2*CA_TILE, sb + 2*CA_TILE + CB_TILE, CKSTR, row, c4, rb[j]);
  }

  for (int c = 0; c < 16; c++){
    __syncthreads();
    uint32_t stg = sb + (uint32_t)(c & 1)*CSTAGE;
    if (c < 15){
      int k0 = (c+1)*32;
      #pragma unroll
      for (int j=0;j<4;j++)
        ra[j] = *(const float4*)(abase + (size_t)(q0 + arow + j*32)*Lc + k0 + ac4);
      #pragma unroll
      for (int j=0;j<2;j++){
        int idx = tid + j*256; int row = idx >> 3; int c4 = (idx & 7) << 2;
        rb[j] = *(const float4*)(bbase + (size_t)row*Lc + k0 + c4);
      }
    }
    uint32_t aRow = (uint32_t)(wm*32 + (lane & 15));
    uint32_t aKof = (uint32_t)((lane >> 4) * 16);
    uint32_t bRow = (uint32_t)(wn*32 + (lane & 7) + ((lane >> 4) * 8));
    uint32_t bKof = (uint32_t)(((lane >> 3) & 1) * 16);
    #pragma unroll
    for (int kk = 0; kk < 2; kk++){
      uint32_t kb = (uint32_t)kk*32;
      uint32_t ah[2][4], al[2][4];
      #pragma unroll
      for (int mi=0; mi<2; mi++){
        uint32_t addr = stg + (aRow + mi*16)*CKSTR + aKof + kb;
        ldm_x4(addr, ah[mi]);
        ldm_x4(addr + CA_TILE, al[mi]);
      }
      uint32_t bhh[2][4], bll[2][4];
      #pragma unroll
      for (int nb=0; nb<2; nb++){
        uint32_t addr = stg + 2*CA_TILE + (bRow + nb*16)*CKSTR + bKof + kb;
        ldm_x4(addr, bhh[nb]);
        ldm_x4(addr + CB_TILE, bll[nb]);
      }
      #pragma unroll
      for (int mi=0; mi<2; mi++)
        #pragma unroll
        for (int ni=0; ni<4; ni++){
          int nb = ni >> 1, hp = (ni & 1) * 2;
          mma_bf16(acc[mi][ni], ah[mi], bhh[nb][hp], bhh[nb][hp+1]);
          mma_bf16(acc[mi][ni], ah[mi], bll[nb][hp], bll[nb][hp+1]);
          mma_bf16(acc[mi][ni], al[mi], bhh[nb][hp], bhh[nb][hp+1]);
        }
    }
    if (c < 15){
      uint32_t nstg = sb + (uint32_t)((c+1) & 1)*CSTAGE;
      #pragma unroll
      for (int j=0;j<4;j++)
        cvt_sts_s(nstg, nstg + CA_TILE, CKSTR, arow + j*32, ac4, ra[j]);
      #pragma unroll
      for (int j=0;j<2;j++){
        int idx = tid + j*256; int row = idx >> 3; int c4 = (idx & 7) << 2;
        cvt_sts_s(nstg + 2*CA_TILE, nstg + 2*CA_TILE + CB_TILE, CKSTR, row, c4, rb[j]);
      }
    }
  }
  #pragma unroll
  for (int mi=0; mi<2; mi++){
    int r0 = b*Lc + q0 + wm*32 + mi*16 + (lane >> 2);
    #pragma unroll
    for (int ni=0; ni<4; ni++){
      int c0 = h*Dkc + wn*32 + ni*8 + (lane & 3)*2;
      *(float2*)(g_ctx + (size_t)r0*Dmod + c0) =
        make_float2(acc[mi][ni][0], acc[mi][ni][1]);
      *(float2*)(g_ctx + (size_t)(r0+8)*Dmod + c0) =
        make_float2(acc[mi][ni][2], acc[mi][ni][3]);
    }
  }
}

// W[k][n] -> Wt[n][k]
__global__ void transpose_kernel(const float* __restrict__ W, float* __restrict__ Wt){
  __shared__ float t[32][33];
  int n0 = blockIdx.x*32, k0 = blockIdx.y*32;
  int tx = threadIdx.x, ty = threadIdx.y;
  for (int i = ty; i < 32; i += 8) t[i][tx] = W[(size_t)(k0+i)*Dmod + n0 + tx];
  __syncthreads();
  for (int i = ty; i < 32; i += 8) Wt[(size_t)(n0+i)*Dmod + k0 + tx] = t[tx][i];
}
__global__ void transpose_v(const float* __restrict__ v, float* __restrict__ vt){
  __shared__ float t[32][33];
  int bh = blockIdx.x, b = bh >> 4, h = bh & 15;
  int l0 = blockIdx.y*32, d0 = blockIdx.z*32;
  int tx = threadIdx.x, ty = threadIdx.y;
  for (int i = ty; i < 32; i += 8)
    t[i][tx] = v[(size_t)(b*Lc + l0 + i)*Dmod + h*Dkc + d0 + tx];
  __syncthreads();
  for (int i = ty; i < 32; i += 8)
    vt[((size_t)bh*64 + d0 + i)*Lc + l0 + tx] = t[tx][i];
}

// ---------------- reductions ----------------
template<int NT>
__device__ __forceinline__ float blockSum(float v, float* red){
  int t = threadIdx.x; red[t] = v; __syncthreads();
  #pragma unroll
  for (int s = NT/2; s > 0; s >>= 1){ if (t < s) red[t] += red[t+s]; __syncthreads(); }
  float r = red[0]; __syncthreads(); return r;
}
template<int NT>
__device__ __forceinline__ float blockMax(float v, float* red){
  int t = threadIdx.x; red[t] = v; __syncthreads();
  #pragma unroll
  for (int s = NT/2; s > 0; s >>= 1){ if (t < s) red[t] = fmaxf(red[t], red[t+s]); __syncthreads(); }
  float r = red[0]; __syncthreads(); return r;
}
__device__ __forceinline__ void atomicMaxF(float* a, float v){
  if (v >= 0.f) atomicMax((int*)a, __float_as_int(v));
  else atomicMin((unsigned int*)a, (unsigned int)__float_as_int(v));
}

__global__ void zero_kernel(float* scal){
  int t = threadIdx.x;
  if (t < 24) scal[t] = 0.f;
  if (t == 0) g_gmax = -3.0e38f;
}

__global__ void gemm16_kernel(const float* __restrict__ A, const float* __restrict__ W,
                              const float* __restrict__ bias, float* __restrict__ out){
  int g = blockIdx.x*256 + threadIdx.x;
  int row = g>>4, h = g&15;
  const float* a = A + (size_t)row*Dmod;
  float acc = 0.f;
  for (int k=0;k<Dmod;k+=4){
    float4 av = *(const float4*)(a+k);
    acc += av.x*W[k*16+h] + av.y*W[(k+1)*16+h] + av.z*W[(k+2)*16+h] + av.w*W[(k+3)*16+h];
  }
  out[g] = acc + bias[h];
}

template<bool HEAD>
__global__ __launch_bounds__(512) void cluster_kernel(
    const float* __restrict__ X, const float* __restrict__ alvArr,
    const float* __restrict__ mu, const float* __restrict__ logvar,
    const float* __restrict__ logprior, float* __restrict__ cpOut,
    float* __restrict__ lpdfOut, float* __restrict__ klOut)
{
  int bh = blockIdx.x; int b = bh/Hc, h = bh%Hc;
  int l = threadIdx.x;
  __shared__ float mu_s[Cc][Dkc], iv_s[Cc][Dkc];
  __shared__ float lvs[Cc], ivs[Cc], lp_s[Cc];
  __shared__ float red[Lc];
  const float* mup = mu + (HEAD?0:h)*Cc*Dkc;
  const float* lvp = logvar + (HEAD?0:h)*Cc*Dkc;
  for (int i=l;i<Cc*Dkc;i+=blockDim.x){ mu_s[i/Dkc][i%Dkc]=mup[i]; iv_s[i/Dkc][i%Dkc]=expf(-lvp[i]); }
  __syncthreads();
  if (l < Cc){
    float ls=0.f, is=0.f;
    for (int d=0;d<Dkc;d++){ ls+=lvp[l*Dkc+d]; is+=iv_s[l][d]; }
    lvs[l]=ls; ivs[l]=is;
  }
  if (l == 0){
    const float* pr = logprior + (HEAD?0:h)*Cc;
    float m=pr[0]; for(int c=1;c<Cc;c++) m=fmaxf(m,pr[c]);
    float s=0.f; for(int c=0;c<Cc;c++) s+=expf(pr[c]-m);
    float lse=m+logf(s);
    for(int c=0;c<Cc;c++) lp_s[c]=pr[c]-lse;
  }
  __syncthreads();
  const float* z = X + ((size_t)(b*Lc+l))*Dmod + h*Dkc;
  float mse[Cc] = {0.f,0.f,0.f,0.f};
  #pragma unroll
  for (int d4=0; d4<Dkc/4; d4++){
    float4 zv = *(const float4*)(z + d4*4);
    #pragma unroll
    for (int c=0;c<Cc;c++){
      float t0=zv.x-mu_s[c][d4*4], t1=zv.y-mu_s[c][d4*4+1];
      float t2=zv.z-mu_s[c][d4*4+2], t3=zv.w-mu_s[c][d4*4+3];
      mse[c]+= t0*t0*iv_s[c][d4*4]+t1*t1*iv_s[c][d4*4+1]+t2*t2*iv_s[c][d4*4+2]+t3*t3*iv_s[c][d4*4+3];
    }
  }
  const float CPI = 64.0f*3.14159265358979323846f;
  float lpdf[Cc]; float mx=-3.0e38f;
  #pragma unroll
  for (int c=0;c<Cc;c++){ lpdf[c] = -0.5f*mse[c] - 0.5f*lvs[c] - CPI + lp_s[c]; mx=fmaxf(mx,lpdf[c]); }
  float se=0.f;
  #pragma unroll
  for (int c=0;c<Cc;c++) se += expf(lpdf[c]-mx);
  float lse = mx + logf(se);
  float kl=0.f; float cp[Cc];
  size_t ob = ((size_t)bh*Lc + l)*Cc;
  #pragma unroll
  for (int c=0;c<Cc;c++){
    float lq = lpdf[c]-lse;
    cp[c] = expf(lq);
    kl += expf(lp_s[c])*(lp_s[c]-lq);
    cpOut[ob+c] = cp[c];
    if (HEAD) lpdfOut[ob+c] = lpdf[c];
  }
  float alv = alvArr[(b*Lc+l)*Hc+h];
  float avar = expf(alv);
  float k2=0.f;
  #pragma unroll
  for (int c=0;c<Cc;c++) k2 += cp[c]*(mse[c] + avar*ivs[c] + lvs[c]);
  kl += 0.5f*k2 - 0.5f*(float)Dkc*(1.0f+alv);
  float tot = blockSum<512>(kl, red);
  if (l==0) atomicAdd(&klOut[b], tot*(1.0f/((float)Hc*Lc)));
  if (HEAD){
    float bm = blockMax<512>(mx, red);
    if (l==0) atomicMaxF(&g_gmax, bm);
  }
}

// ---------------- div via 4x4 Gram ----------------
__global__ __launch_bounds__(512) void div_fast(const float4* __restrict__ cp, float* __restrict__ divOut){
  int bh = blockIdx.x; int b = bh/Hc;
  __shared__ float red[512];
  float4 p = cp[(size_t)bh*Lc + threadIdx.x];
  float g = p.x*p.x + p.y*p.y + p.z*p.z + p.w*p.w;
  float m[10] = {p.x*p.x, p.x*p.y, p.x*p.z, p.x*p.w,
                 p.y*p.y, p.y*p.z, p.y*p.w,
                 p.z*p.z, p.z*p.w, p.w*p.w};
  float dterm = 1.25f*(g-1.0f)*(g-1.0f) - 0.75f*g*g;
  float Ms[10];
  #pragma unroll
  for (int i=0;i<10;i++) Ms[i] = blockSum<512>(m[i], red);
  float dsum = blockSum<512>(dterm, red);
  if (threadIdx.x == 0){
    float frob = Ms[0]*Ms[0] + Ms[4]*Ms[4] + Ms[7]*Ms[7] + Ms[9]*Ms[9]
      + 2.0f*(Ms[1]*Ms[1] + Ms[2]*Ms[2] + Ms[3]*Ms[3] + Ms[5]*Ms[5] + Ms[6]*Ms[6] + Ms[8]*Ms[8]);
    atomicAdd(&divOut[b], (0.75f*frob + dsum) * (1.0f/((float)Hc*Lc*Lc)));
  }
}

// ---------------- fused softmax*mask + renorm + head-mean ----------------
__global__ __launch_bounds__(512) void softmax_mean(float* __restrict__ am){
  __shared__ float mat[16][512];
  int r = blockIdx.x;
  int b = r >> 9, q = r & 511;
  int tid = threadIdx.x, w = tid >> 5, lane = tid & 31;
  int bh = b*Hc + w;
  float* row = g_attn + ((size_t)bh*Lc + q)*Lc;
  const float4* cp4 = ((const float4*)g_cpq) + (size_t)bh*Lc;
  float4 cq = cp4[q];
  float s[16];
  #pragma unroll
  for (int t=0;t<16;t++) s[t] = row[lane + t*32];
  float mx = -3.0e38f;
  #pragma unroll
  for (int t=0;t<16;t++) mx = fmaxf(mx, s[t]);
  mx = wmax32(mx);
  float es = 0.f;
  #pragma unroll
  for (int t=0;t<16;t++){ s[t] = fexp(s[t]-mx); es += s[t]; }
  es = wsum32(es);
  float inv_se = 1.0f/es;
  float ts = 0.f;
  #pragma unroll
  for (int t=0;t<16;t++){
    float4 ck = cp4[lane + t*32];
    float m = cq.x*ck.x + cq.y*ck.y + cq.z*ck.z + cq.w*ck.w;
    s[t] = s[t]*inv_se*m;
    ts += s[t];
  }
  ts = wsum32(ts);
  float inv = 1.0f/(ts + 1e-6f);
  #pragma unroll
  for (int t=0;t<16;t++){
    float f = s[t]*inv;
    row[lane + t*32] = f;
    mat[w][lane + t*32] = f;
  }
  __syncthreads();
  float sum = 0.f;
  #pragma unroll
  for (int h=0;h<16;h++) sum += mat[h][tid];
  am[(size_t)r*Lc + tid] = sum * (1.0f/16.0f);
}

__global__ __launch_bounds__(512) void pdf_wsum_kernel(){
  int bh=blockIdx.x; int l=threadIdx.x;
  __shared__ float red[512];
  float gm = g_gmax;
  int base = (bh*Lc+l)*Cc;
  float p=0.f;
  #pragma unroll
  for (int c=0;c<Cc;c++) p += fexp(g_lpdf[base+c]-gm);
  g_pdf[bh*Lc+l]=p;
  #pragma unroll
  for (int c=0;c<Cc;c++){
    float s = blockSum<512>(g_cph[base+c]*p, red);
    if (l==0) g_wsum[bh*Cc+c]=s;
  }
}

__global__ __launch_bounds__(512) void mi_kernel(float* __restrict__ miOut){
  int wid = threadIdx.x >> 5, lane = threadIdx.x & 31;
  int bl = blockIdx.x*16 + wid;
  int b = bl >> 9, l = bl & 511;
  float cpv[Cc]={0,0,0,0}, mp[Cc]={0,0,0,0};
  if (lane < Hc){
    int base = ((b*Hc+lane)*Lc+l)*Cc;
    float pd = g_pdf[(b*Hc+lane)*Lc+l];
    #pragma unroll
    for (int c=0;c<Cc;c++){
      cpv[c]=g_cph[base+c];
      mp[c]=cpv[c]*pd/fmaxf(g_wsum[(b*Hc+lane)*Cc+c],1e-6f);
    }
  }
  float acc=0.f;
  for (int j=0;j<Hc;j++){
    float c0=__shfl_sync(0xffffffffu,cpv[0],j);
    float c1=__shfl_sync(0xffffffffu,cpv[1],j);
    float c2=__shfl_sync(0xffffffffu,cpv[2],j);
    float c3=__shfl_sync(0xffffffffu,cpv[3],j);
    if (lane<Hc && lane!=j){
      float p = fminf(mp[0]*c0+mp[1]*c1+mp[2]*c2+mp[3]*c3, 1.0f);
      acc += logf(1.0f-p+1e-6f);
    }
  }
  #pragma unroll
  for (int o=16;o>0;o>>=1) acc += __shfl_down_sync(0xffffffffu,acc,o);
  if (lane==0) atomicAdd(&miOut[b], acc*(-10.0f/((float)Lc*Hc*Hc)));
}

__global__ __launch_bounds__(512) void diag_kernel(float* __restrict__ miOut){
  int bh=blockIdx.x; int b=bh>>4;
  __shared__ float4 cps[Lc];
  __shared__ float red[512];
  for (int i=threadIdx.x;i<Lc;i+=512) cps[i]=((const float4*)g_cph)[(size_t)bh*Lc+i];
  __syncthreads();
  int q=threadIdx.x;
  float4 a=cps[q];
  float s=0.f, dq=0.f;
  for (int k=0;k<Lc;k++){
    float4 c=cps[k];
    float g=a.x*c.x+a.y*c.y+a.z*c.z+a.w*c.w;
    if (k==q) dq=g;
    s += fexp(g);
  }
  float tot = blockSum<512>(dq-logf(s), red);
  if (threadIdx.x==0) atomicAdd(&miOut[b], -tot/((float)Hc*Lc));
}

extern "C" void kernel_launch(void* const* d_in, const int* in_sizes, int n_in,
                              void* d_out, int out_size){
  const float *query=(const float*)d_in[0], *key=(const float*)d_in[1], *value=(const float*)d_in[2];
  const float *Wq=(const float*)d_in[3], *bq=(const float*)d_in[4];
  const float *Wk=(const float*)d_in[5], *bk=(const float*)d_in[6];
  const float *Wv=(const float*)d_in[7], *bv=(const float*)d_in[8];
  const float *Wo=(const float*)d_in[9], *bo=(const float*)d_in[10];
  const float *Wsem=(const float*)d_in[11], *bsem=(const float*)d_in[12];
  const float *Whead=(const float*)d_in[13], *bhead=(const float*)d_in[14];
  const float *tmu=(const float*)d_in[15], *tlv=(const float*)d_in[16], *tlp=(const float*)d_in[17];
  const float *hmu=(const float*)d_in[18], *hlv=(const float*)d_in[19], *hlp=(const float*)d_in[20];
  float* out = (float*)d_out;
  float* am  = out + OUT_N;
  float* kl  = out + KL_OFF;
  float* dv  = out + KL_OFF + 8;
  float* mi  = out + KL_OFF + 16;

  float *pq,*pk,*pv,*pvt,*pctx,*pwt,*pwt2,*pwt3,*pwt4,*palv,*palvh,*pcpq,*pcph,*plpdf;
  cudaGetSymbolAddress((void**)&pq, g_q);
  cudaGetSymbolAddress((void**)&pk, g_k);
  cudaGetSymbolAddress((void**)&pv, g_v);
  cudaGetSymbolAddress((void**)&pvt, g_vt);
  cudaGetSymbolAddress((void**)&pctx, g_ctx);
  cudaGetSymbolAddress((void**)&pwt, g_wt);
  cudaGetSymbolAddress((void**)&pwt2, g_wt2);
  cudaGetSymbolAddress((void**)&pwt3, g_wt3);
  cudaGetSymbolAddress((void**)&pwt4, g_wt4);
  cudaGetSymbolAddress((void**)&palv, g_alv);
  cudaGetSymbolAddress((void**)&palvh, g_alvh);
  cudaGetSymbolAddress((void**)&pcpq, g_cpq);
  cudaGetSymbolAddress((void**)&pcph, g_cph);
  cudaGetSymbolAddress((void**)&plpdf, g_lpdf);

  cudaFuncSetAttribute(gemm_mma, cudaFuncAttributeMaxDynamicSharedMemorySize, SMEM_MMA);
  cudaFuncSetAttribute(scores_mma, cudaFuncAttributeMaxDynamicSharedMemorySize, SMEM_SC);
  cudaFuncSetAttribute(ctx_mma, cudaFuncAttributeMaxDynamicSharedMemorySize, SMEM_CTX);

  int M = Bc*Lc;
  dim3 gt(32, 32), bt(32, 8);
  dim3 gg(Dmod/128, M/128);

  zero_kernel<<<1, 32>>>(kl);
  transpose_kernel<<<gt, bt>>>(Wq, pwt);
  transpose_kernel<<<gt, bt>>>(Wk, pwt2);
  transpose_kernel<<<gt, bt>>>(Wv, pwt3);
  transpose_kernel<<<gt, bt>>>(Wo, pwt4);
  gemm_mma<<<gg, 256, SMEM_MMA>>>(query, pwt, bq, pq);
  gemm_mma<<<gg, 256, SMEM_MMA>>>(key, pwt2, bk, pk);
  gemm_mma<<<gg, 256, SMEM_MMA>>>(value, pwt3, bv, pv);
  transpose_v<<<dim3(Bc*Hc, Lc/32, Dkc/32), bt>>>(pv, pvt);
  gemm16_kernel<<<M*16/256, 256>>>(pq, Wsem, bsem, palv);
  cluster_kernel<false><<<Bc*Hc, 512>>>(pq, palv, tmu, tlv, tlp, pcpq, nullptr, kl);
  div_fast<<<Bc*Hc, 512>>>((const float4*)pcpq, dv);
  scores_mma<<<dim3(Bc*Hc, Lc/128, Lc/128), 256, SMEM_SC>>>();
  softmax_mean<<<Bc*Lc, 512>>>(am);
  ctx_mma<<<dim3(Bc*Hc, Lc/128), 256, SMEM_CTX>>>(pvt);
  gemm16_kernel<<<M*16/256, 256>>>(pctx, Whead, bhead, palvh);
  cluster_kernel<true><<<Bc*Hc, 512>>>(pctx, palvh, hmu, hlv, hlp, pcph, plpdf, kl);
  div_fast<<<Bc*Hc, 512>>>((const float4*)pcph, dv);
  pdf_wsum_kernel<<<Bc*Hc, 512>>>();
  mi_kernel<<<Bc*Lc/16, 512>>>(mi);
  diag_kernel<<<Bc*Hc, 512>>>(mi);
  gemm_mma<<<gg, 256, SMEM_MMA>>>(pctx, pwt4, bo, out);
}

// round 16
// speedup vs baseline: 1.0373x; 1.0114x over previous
#include <cuda_runtime.h>
#include <cuda_bf16.h>
#include <cstdint>
#include <math.h>

#define Bc 8
#define Lc 512
#define Dmod 1024
#define Hc 16
#define Cc 4
#define Dkc 64
#define OUT_N  (Bc*Lc*Dmod)
#define AM_N   (Bc*Lc*Lc)
#define KL_OFF (OUT_N + AM_N)

__device__ float g_q[OUT_N];
__device__ float g_k[OUT_N];
__device__ float g_v[OUT_N];
__device__ float g_vt[OUT_N];
__device__ float g_ctx[OUT_N];
__device__ float g_wt[Dmod*Dmod];
__device__ float g_wt2[Dmod*Dmod];
__device__ float g_wt3[Dmod*Dmod];
__device__ float g_wt4[Dmod*Dmod];
__device__ float g_alv[Bc*Lc*Hc];
__device__ float g_alvh[Bc*Lc*Hc];
__device__ float g_cpq[Bc*Hc*Lc*Cc];
__device__ float g_cph[Bc*Hc*Lc*Cc];
__device__ float g_lpdf[Bc*Hc*Lc*Cc];
__device__ float g_pdf[Bc*Hc*Lc];
__device__ float g_wsum[Bc*Hc*Cc];
__device__ float g_attn[(size_t)Bc*Hc*Lc*Lc];
__device__ float g_gmax;

// ---------------- portable PTX helpers (sm_80+) ----------------
__device__ __forceinline__ uint32_t smem_to_u32(const void* p) {
  uint32_t a;
  asm("{ .reg .u64 t; cvta.to.shared.u64 t, %1; cvt.u32.u64 %0, t; }" : "=r"(a) : "l"(p));
  return a;
}
__device__ __forceinline__ void ldm_x4(uint32_t addr, uint32_t r[4]){
  asm volatile("ldmatrix.sync.aligned.m8n8.x4.shared.b16 {%0,%1,%2,%3}, [%4];"
    : "=r"(r[0]),"=r"(r[1]),"=r"(r[2]),"=r"(r[3]) : "r"(addr));
}
__device__ __forceinline__ void mma_bf16(float c[4], const uint32_t a[4], uint32_t b0, uint32_t b1){
  asm volatile("mma.sync.aligned.m16n8k16.row.col.f32.bf16.bf16.f32 "
    "{%0,%1,%2,%3}, {%4,%5,%6,%7}, {%8,%9}, {%0,%1,%2,%3};"
    : "+f"(c[0]),"+f"(c[1]),"+f"(c[2]),"+f"(c[3])
    : "r"(a[0]),"r"(a[1]),"r"(a[2]),"r"(a[3]), "r"(b0),"r"(b1));
}
__device__ __forceinline__ uint32_t packbf(float a, float b){ // lo16=a, hi16=b
  uint32_t r; asm("cvt.rn.bf16x2.f32 %0, %1, %2;" : "=r"(r) : "f"(b), "f"(a)); return r;
}
__device__ __forceinline__ void sts_v2(uint32_t a, uint32_t x, uint32_t y){
  asm volatile("st.shared.v2.b32 [%0], {%1, %2};" :: "r"(a), "r"(x), "r"(y) : "memory");
}
__device__ __forceinline__ float fexp(float x){
  x = fmaxf(x, -87.0f);
  float y = x * 1.4426950408889634f;
  float n = rintf(y);
  float f = (y - n) * 0.6931471805599453f;
  float p = 0.0013888889f;
  p = fmaf(p, f, 0.0083333333f);
  p = fmaf(p, f, 0.0416666667f);
  p = fmaf(p, f, 0.1666666667f);
  p = fmaf(p, f, 0.5f);
  p = fmaf(p, f, 1.0f);
  p = fmaf(p, f, 1.0f);
  int e = (int)n;
  return p * __int_as_float((e + 127) << 23);
}
__device__ __forceinline__ float wsum32(float v){
  #pragma unroll
  for (int o=16;o>0;o>>=1) v += __shfl_xor_sync(0xffffffffu, v, o);
  return v;
}
__device__ __forceinline__ float wmax32(float v){
  #pragma unroll
  for (int o=16;o>0;o>>=1) v = fmaxf(v, __shfl_xor_sync(0xffffffffu, v, o));
  return v;
}
__device__ __forceinline__ void cvt_sts_s(uint32_t hi_b, uint32_t lo_b, uint32_t stride,
                                          int row, int c4, float4 v){
  uint32_t h0 = packbf(v.x, v.y), h1 = packbf(v.z, v.w);
  float rx = v.x - __uint_as_float(h0 << 16);
  float ry = v.y - __uint_as_float(h0 & 0xFFFF0000u);
  float rz = v.z - __uint_as_float(h1 << 16);
  float rw = v.w - __uint_as_float(h1 & 0xFFFF0000u);
  uint32_t l0 = packbf(rx, ry), l1 = packbf(rz, rw);
  uint32_t off = (uint32_t)row*stride + (uint32_t)c4*2;
  sts_v2(hi_b + off, h0, h1);
  sts_v2(lo_b + off, l0, l1);
}

// ---------------- tensor-core GEMM: C(4096x1024) = A @ Wt^T + bias ----------------
#define KSTR 80
#define TILE_BY (128*KSTR)
#define STAGE_BY (4*TILE_BY)
#define SMEM_MMA (2*STAGE_BY)

__global__ __launch_bounds__(256, 1) void gemm_mma(
    const float* __restrict__ A, const float* __restrict__ Wt,
    const float* __restrict__ bias, float* __restrict__ Cmat)
{
  extern __shared__ char smem[];
  uint32_t sb = smem_to_u32(smem);
  int tid = threadIdx.x, lane = tid & 31, wid = tid >> 5;
  int wm = wid & 3, wn = wid >> 2;
  int brow = blockIdx.y * 128, bcol = blockIdx.x * 128;

  float acc[2][8][4];
  #pragma unroll
  for (int i=0;i<2;i++)
    #pragma unroll
    for (int j=0;j<8;j++)
      #pragma unroll
      for (int q=0;q<4;q++) acc[i][j][q]=0.f;

  int lrow = tid >> 3, lkc = tid & 7;
  float4 ra[4], rb[4];
  #pragma unroll
  for (int j=0;j<4;j++){
    int row = lrow + j*32;
    ra[j] = *(const float4*)(A  + (size_t)(brow+row)*Dmod + lkc*4);
    rb[j] = *(const float4*)(Wt + (size_t)(bcol+row)*Dmod + lkc*4);
  }
  #pragma unroll
  for (int j=0;j<4;j++){
    cvt_sts_s(sb,             sb +   TILE_BY, KSTR, lrow + j*32, lkc*4, ra[j]);
    cvt_sts_s(sb + 2*TILE_BY, sb + 3*TILE_BY, KSTR, lrow + j*32, lkc*4, rb[j]);
  }

  for (int c = 0; c < 32; c++){
    __syncthreads();
    uint32_t stg = sb + (uint32_t)(c & 1)*STAGE_BY;
    if (c < 31){
      int k0 = (c+1)*32;
      #pragma unroll
      for (int j=0;j<4;j++){
        int row = lrow + j*32;
        ra[j] = *(const float4*)(A  + (size_t)(brow+row)*Dmod + k0 + lkc*4);
        rb[j] = *(const float4*)(Wt + (size_t)(bcol+row)*Dmod + k0 + lkc*4);
      }
    }
    uint32_t aRow = (uint32_t)(wm*32 + (lane & 15));
    uint32_t aKof = (uint32_t)((lane >> 4) * 16);
    uint32_t bRow = (uint32_t)(wn*64 + (lane & 7) + ((lane >> 4) * 8));
    uint32_t bKof = (uint32_t)(((lane >> 3) & 1) * 16);
    #pragma unroll
    for (int kk = 0; kk < 2; kk++){
      uint32_t kb = (uint32_t)kk*32;
      uint32_t ah[2][4], al[2][4];
      #pragma unroll
      for (int mi=0; mi<2; mi++){
        uint32_t addr = stg + (aRow + mi*16)*KSTR + aKof + kb;
        ldm_x4(addr, ah[mi]);
        ldm_x4(addr + TILE_BY, al[mi]);
      }
      uint32_t bh[4][4], bl[4][4];
      #pragma unroll
      for (int nb=0; nb<4; nb++){
        uint32_t addr = stg + 2*TILE_BY + (bRow + nb*16)*KSTR + bKof + kb;
        ldm_x4(addr, bh[nb]);
        ldm_x4(addr + TILE_BY, bl[nb]);
      }
      #pragma unroll
      for (int mi=0; mi<2; mi++)
        #pragma unroll
        for (int ni=0; ni<8; ni++){
          int nb = ni >> 1, hp = (ni & 1) * 2;
          mma_bf16(acc[mi][ni], ah[mi], bh[nb][hp], bh[nb][hp+1]);
          mma_bf16(acc[mi][ni], ah[mi], bl[nb][hp], bl[nb][hp+1]);
          mma_bf16(acc[mi][ni], al[mi], bh[nb][hp], bh[nb][hp+1]);
        }
    }
    if (c < 31){
      uint32_t nstg = sb + (uint32_t)((c+1) & 1)*STAGE_BY;
      #pragma unroll
      for (int j=0;j<4;j++){
        cvt_sts_s(nstg,             nstg +   TILE_BY, KSTR, lrow + j*32, lkc*4, ra[j]);
        cvt_sts_s(nstg + 2*TILE_BY, nstg + 3*TILE_BY, KSTR, lrow + j*32, lkc*4, rb[j]);
      }
    }
  }

  #pragma unroll
  for (int mi=0; mi<2; mi++){
    int r0 = brow + wm*32 + mi*16 + (lane >> 2);
    #pragma unroll
    for (int ni=0; ni<8; ni++){
      int c0 = bcol + wn*64 + ni*8 + (lane & 3)*2;
      float b0 = bias[c0], b1 = bias[c0+1];
      *(float2*)(Cmat + (size_t)r0*Dmod + c0) =
        make_float2(acc[mi][ni][0] + b0, acc[mi][ni][1] + b1);
      *(float2*)(Cmat + (size_t)(r0+8)*Dmod + c0) =
        make_float2(acc[mi][ni][2] + b0, acc[mi][ni][3] + b1);
    }
  }
}

// ---------------- scores via MMA: S = Z K^T / 8 ----------------
#define SKSTR 144
#define STILE_B (128*SKSTR)
#define SMEM_SC (4*STILE_B)
__global__ __launch_bounds__(256) void scores_mma(){
  extern __shared__ char smem[];
  uint32_t sb = smem_to_u32(smem);
  int bh = blockIdx.x, b = bh >> 4, h = bh & 15;
  int q0 = blockIdx.y << 7, k0 = blockIdx.z << 7;
  int tid = threadIdx.x, lane = tid & 31, wid = tid >> 5;
  int wm = wid & 3, wn = wid >> 2;
  #pragma unroll
  for (int j=0;j<8;j++){
    int idx = tid + j*256; int row = idx >> 4; int c4 = (idx & 15) << 2;
    float4 v = *(const float4*)(g_q + ((size_t)(b*Lc + q0 + row))*Dmod + h*Dkc + c4);
    cvt_sts_s(sb, sb + STILE_B, SKSTR, row, c4, v);
    float4 w = *(const float4*)(g_k + ((size_t)(b*Lc + k0 + row))*Dmod + h*Dkc + c4);
    cvt_sts_s(sb + 2*STILE_B, sb + 3*STILE_B, SKSTR, row, c4, w);
  }
  __syncthreads();
  float acc[2][8][4];
  #pragma unroll
  for (int i=0;i<2;i++)
    #pragma unroll
    for (int j=0;j<8;j++)
      #pragma unroll
      for (int q=0;q<4;q++) acc[i][j][q]=0.f;
  uint32_t aRow = (uint32_t)(wm*32 + (lane & 15));
  uint32_t aKof = (uint32_t)((lane >> 4) * 16);
  uint32_t bRow = (uint32_t)(wn*64 + (lane & 7) + ((lane >> 4) * 8));
  uint32_t bKof = (uint32_t)(((lane >> 3) & 1) * 16);
  #pragma unroll
  for (int kk = 0; kk < 4; kk++){
    uint32_t kb = (uint32_t)kk*32;
    uint32_t ah[2][4], al[2][4];
    #pragma unroll
    for (int mi=0; mi<2; mi++){
      uint32_t addr = sb + (aRow + mi*16)*SKSTR + aKof + kb;
      ldm_x4(addr, ah[mi]);
      ldm_x4(addr + STILE_B, al[mi]);
    }
    uint32_t bhh[4][4], bll[4][4];
    #pragma unroll
    for (int nb=0; nb<4; nb++){
      uint32_t addr = sb + 2*STILE_B + (bRow + nb*16)*SKSTR + bKof + kb;
      ldm_x4(addr, bhh[nb]);
      ldm_x4(addr + STILE_B, bll[nb]);
    }
    #pragma unroll
    for (int mi=0; mi<2; mi++)
      #pragma unroll
      for (int ni=0; ni<8; ni++){
        int nb = ni >> 1, hp = (ni & 1) * 2;
        mma_bf16(acc[mi][ni], ah[mi], bhh[nb][hp], bhh[nb][hp+1]);
        mma_bf16(acc[mi][ni], ah[mi], bll[nb][hp], bll[nb][hp+1]);
        mma_bf16(acc[mi][ni], al[mi], bhh[nb][hp], bhh[nb][hp+1]);
      }
  }
  #pragma unroll
  for (int mi=0; mi<2; mi++){
    int r0 = q0 + wm*32 + mi*16 + (lane >> 2);
    #pragma unroll
    for (int ni=0; ni<8; ni++){
      int c0 = k0 + wn*64 + ni*8 + (lane & 3)*2;
      *(float2*)(g_attn + ((size_t)bh*Lc + r0)*Lc + c0) =
        make_float2(acc[mi][ni][0]*0.125f, acc[mi][ni][1]*0.125f);
      *(float2*)(g_attn + ((size_t)bh*Lc + r0 + 8)*Lc + c0) =
        make_float2(acc[mi][ni][2]*0.125f, acc[mi][ni][3]*0.125f);
    }
  }
}

// ---------------- ctx via MMA: ctx = attn @ V ----------------
#define CKSTR 80
#define CA_TILE (128*CKSTR)
#define CB_TILE (64*CKSTR)
#define CSTAGE (2*CA_TILE + 2*CB_TILE)
#define SMEM_CTX (2*CSTAGE)
__global__ __launch_bounds__(256) void ctx_mma(const float* __restrict__ vt){
  extern __shared__ char smem[];
  uint32_t sb = smem_to_u32(smem);
  int bh = blockIdx.x, b = bh >> 4, h = bh & 15;
  int q0 = blockIdx.y << 7;
  int tid = threadIdx.x, lane = tid & 31, wid = tid >> 5;
  int wm = wid & 3, wn = wid >> 2;
  float acc[2][4][4];
  #pragma unroll
  for (int i=0;i<2;i++)
    #pragma unroll
    for (int j=0;j<4;j++)
      #pragma unroll
      for (int q=0;q<4;q++) acc[i][j][q]=0.f;

  const float* abase = g_attn + (size_t)bh*Lc*Lc;
  const float* bbase = vt + (size_t)bh*64*Lc;
  int arow = tid >> 3, ac4 = (tid & 7) << 2;
  float4 ra[4], rb[2];
  #pragma unroll
  for (int j=0;j<4;j++)
    ra[j] = *(const float4*)(abase + (size_t)(q0 + arow + j*32)*Lc + ac4);
  #pragma unroll
  for (int j=0;j<2;j++){
    int idx = tid + j*256; int row = idx >> 3; int c4 = (idx & 7) << 2;
    rb[j] = *(const float4*)(bbase + (size_t)row*Lc + c4);
  }
  #pragma unroll
  for (int j=0;j<4;j++)
    cvt_sts_s(sb, sb + CA_TILE, CKSTR, arow + j*32, ac4, ra[j]);
  #pragma unroll
  for (int j=0;j<2;j++){
    int idx = tid + j*256; int row = idx >> 3; int c4 = (idx & 7) << 2;
    cvt_sts_s(sb + 2*CA_TILE, sb + 2*CA_TILE + CB_TILE, CKSTR, row, c4, rb[j]);
  }

  for (int c = 0; c < 16; c++){
    __syncthreads();
    uint32_t stg = sb + (uint32_t)(c & 1)*CSTAGE;
    if (c < 15){
      int k0 = (c+1)*32;
      #pragma unroll
      for (int j=0;j<4;j++)
        ra[j] = *(const float4*)(abase + (size_t)(q0 + arow + j*32)*Lc + k0 + ac4);
      #pragma unroll
      for (int j=0;j<2;j++){
        int idx = tid + j*256; int row = idx >> 3; int c4 = (idx & 7) << 2;
        rb[j] = *(const float4*)(bbase + (size_t)row*Lc + k0 + c4);
      }
    }
    uint32_t aRow = (uint32_t)(wm*32 + (lane & 15));
    uint32_t aKof = (uint32_t)((lane >> 4) * 16);
    uint32_t bRow = (uint32_t)(wn*32 + (lane & 7) + ((lane >> 4) * 8));
    uint32_t bKof = (uint32_t)(((lane >> 3) & 1) * 16);
    #pragma unroll
    for (int kk = 0; kk < 2; kk++){
      uint32_t kb = (uint32_t)kk*32;
      uint32_t ah[2][4], al[2][4];
      #pragma unroll
      for (int mi=0; mi<2; mi++){
        uint32_t addr = stg + (aRow + mi*16)*CKSTR + aKof + kb;
        ldm_x4(addr, ah[mi]);
        ldm_x4(addr + CA_TILE, al[mi]);
      }
      uint32_t bhh[2][4], bll[2][4];
      #pragma unroll
      for (int nb=0; nb<2; nb++){
        uint32_t addr = stg + 2*CA_TILE + (bRow + nb*16)*CKSTR + bKof + kb;
        ldm_x4(addr, bhh[nb]);
        ldm_x4(addr + CB_TILE, bll[nb]);
      }
      #pragma unroll
      for (int mi=0; mi<2; mi++)
        #pragma unroll
        for (int ni=0; ni<4; ni++){
          int nb = ni >> 1, hp = (ni & 1) * 2;
          mma_bf16(acc[mi][ni], ah[mi], bhh[nb][hp], bhh[nb][hp+1]);
          mma_bf16(acc[mi][ni], ah[mi], bll[nb][hp], bll[nb][hp+1]);
          mma_bf16(acc[mi][ni], al[mi], bhh[nb][hp], bhh[nb][hp+1]);
        }
    }
    if (c < 15){
      uint32_t nstg = sb + (uint32_t)((c+1) & 1)*CSTAGE;
      #pragma unroll
      for (int j=0;j<4;j++)
        cvt_sts_s(nstg, nstg + CA_TILE, CKSTR, arow + j*32, ac4, ra[j]);
      #pragma unroll
      for (int j=0;j<2;j++){
        int idx = tid + j*256; int row = idx >> 3; int c4 = (idx & 7) << 2;
        cvt_sts_s(nstg + 2*CA_TILE, nstg + 2*CA_TILE + CB_TILE, CKSTR, row, c4, rb[j]);
      }
    }
  }
  #pragma unroll
  for (int mi=0; mi<2; mi++){
    int r0 = b*Lc + q0 + wm*32 + mi*16 + (lane >> 2);
    #pragma unroll
    for (int ni=0; ni<4; ni++){
      int c0 = h*Dkc + wn*32 + ni*8 + (lane & 3)*2;
      *(float2*)(g_ctx + (size_t)r0*Dmod + c0) =
        make_float2(acc[mi][ni][0], acc[mi][ni][1]);
      *(float2*)(g_ctx + (size_t)(r0+8)*Dmod + c0) =
        make_float2(acc[mi][ni][2], acc[mi][ni][3]);
    }
  }
}

// W[k][n] -> Wt[n][k]
__global__ void transpose_kernel(const float* __restrict__ W, float* __restrict__ Wt){
  __shared__ float t[32][33];
  int n0 = blockIdx.x*32, k0 = blockIdx.y*32;
  int tx = threadIdx.x, ty = threadIdx.y;
  for (int i = ty; i < 32; i += 8) t[i][tx] = W[(size_t)(k0+i)*Dmod + n0 + tx];
  __syncthreads();
  for (int i = ty; i < 32; i += 8) Wt[(size_t)(n0+i)*Dmod + k0 + tx] = t[tx][i];
}
__global__ void transpose_v(const float* __restrict__ v, float* __restrict__ vt){
  __shared__ float t[32][33];
  int bh = blockIdx.x, b = bh >> 4, h = bh & 15;
  int l0 = blockIdx.y*32, d0 = blockIdx.z*32;
  int tx = threadIdx.x, ty = threadIdx.y;
  for (int i = ty; i < 32; i += 8)
    t[i][tx] = v[(size_t)(b*Lc + l0 + i)*Dmod + h*Dkc + d0 + tx];
  __syncthreads();
  for (int i = ty; i < 32; i += 8)
    vt[((size_t)bh*64 + d0 + i)*Lc + l0 + tx] = t[tx][i];
}

// ---------------- reductions ----------------
template<int NT>
__device__ __forceinline__ float blockSum(float v, float* red){
  int t = threadIdx.x; red[t] = v; __syncthreads();
  #pragma unroll
  for (int s = NT/2; s > 0; s >>= 1){ if (t < s) red[t] += red[t+s]; __syncthreads(); }
  float r = red[0]; __syncthreads(); return r;
}
template<int NT>
__device__ __forceinline__ float blockMax(float v, float* red){
  int t = threadIdx.x; red[t] = v; __syncthreads();
  #pragma unroll
  for (int s = NT/2; s > 0; s >>= 1){ if (t < s) red[t] = fmaxf(red[t], red[t+s]); __syncthreads(); }
  float r = red[0]; __syncthreads(); return r;
}
__device__ __forceinline__ void atomicMaxF(float* a, float v){
  if (v >= 0.f) atomicMax((int*)a, __float_as_int(v));
  else atomicMin((unsigned int*)a, (unsigned int)__float_as_int(v));
}

__global__ void zero_kernel(float* scal){
  int t = threadIdx.x;
  if (t < 24) scal[t] = 0.f;
  if (t == 0) g_gmax = -3.0e38f;
}

__global__ void gemm16_kernel(const float* __restrict__ A, const float* __restrict__ W,
                              const float* __restrict__ bias, float* __restrict__ out){
  int g = blockIdx.x*256 + threadIdx.x;
  int row = g>>4, h = g&15;
  const float* a = A + (size_t)row*Dmod;
  float acc = 0.f;
  for (int k=0;k<Dmod;k+=4){
    float4 av = *(const float4*)(a+k);
    acc += av.x*W[k*16+h] + av.y*W[(k+1)*16+h] + av.z*W[(k+2)*16+h] + av.w*W[(k+3)*16+h];
  }
  out[g] = acc + bias[h];
}

template<bool HEAD>
__global__ __launch_bounds__(512) void cluster_kernel(
    const float* __restrict__ X, const float* __restrict__ alvArr,
    const float* __restrict__ mu, const float* __restrict__ logvar,
    const float* __restrict__ logprior, float* __restrict__ cpOut,
    float* __restrict__ lpdfOut, float* __restrict__ klOut)
{
  int bh = blockIdx.x; int b = bh/Hc, h = bh%Hc;
  int l = threadIdx.x;
  __shared__ float mu_s[Cc][Dkc], iv_s[Cc][Dkc];
  __shared__ float lvs[Cc], ivs[Cc], lp_s[Cc];
  __shared__ float red[Lc];
  const float* mup = mu + (HEAD?0:h)*Cc*Dkc;
  const float* lvp = logvar + (HEAD?0:h)*Cc*Dkc;
  for (int i=l;i<Cc*Dkc;i+=blockDim.x){ mu_s[i/Dkc][i%Dkc]=mup[i]; iv_s[i/Dkc][i%Dkc]=expf(-lvp[i]); }
  __syncthreads();
  if (l < Cc){
    float ls=0.f, is=0.f;
    for (int d=0;d<Dkc;d++){ ls+=lvp[l*Dkc+d]; is+=iv_s[l][d]; }
    lvs[l]=ls; ivs[l]=is;
  }
  if (l == 0){
    const float* pr = logprior + (HEAD?0:h)*Cc;
    float m=pr[0]; for(int c=1;c<Cc;c++) m=fmaxf(m,pr[c]);
    float s=0.f; for(int c=0;c<Cc;c++) s+=expf(pr[c]-m);
    float lse=m+logf(s);
    for(int c=0;c<Cc;c++) lp_s[c]=pr[c]-lse;
  }
  __syncthreads();
  const float* z = X + ((size_t)(b*Lc+l))*Dmod + h*Dkc;
  float mse[Cc] = {0.f,0.f,0.f,0.f};
  #pragma unroll
  for (int d4=0; d4<Dkc/4; d4++){
    float4 zv = *(const float4*)(z + d4*4);
    #pragma unroll
    for (int c=0;c<Cc;c++){
      float t0=zv.x-mu_s[c][d4*4], t1=zv.y-mu_s[c][d4*4+1];
      float t2=zv.z-mu_s[c][d4*4+2], t3=zv.w-mu_s[c][d4*4+3];
      mse[c]+= t0*t0*iv_s[c][d4*4]+t1*t1*iv_s[c][d4*4+1]+t2*t2*iv_s[c][d4*4+2]+t3*t3*iv_s[c][d4*4+3];
    }
  }
  const float CPI = 64.0f*3.14159265358979323846f;
  float lpdf[Cc]; float mx=-3.0e38f;
  #pragma unroll
  for (int c=0;c<Cc;c++){ lpdf[c] = -0.5f*mse[c] - 0.5f*lvs[c] - CPI + lp_s[c]; mx=fmaxf(mx,lpdf[c]); }
  float se=0.f;
  #pragma unroll
  for (int c=0;c<Cc;c++) se += expf(lpdf[c]-mx);
  float lse = mx + logf(se);
  float kl=0.f; float cp[Cc];
  size_t ob = ((size_t)bh*Lc + l)*Cc;
  #pragma unroll
  for (int c=0;c<Cc;c++){
    float lq = lpdf[c]-lse;
    cp[c] = expf(lq);
    kl += expf(lp_s[c])*(lp_s[c]-lq);
    cpOut[ob+c] = cp[c];
    if (HEAD) lpdfOut[ob+c] = lpdf[c];
  }
  float alv = alvArr[(b*Lc+l)*Hc+h];
  float avar = expf(alv);
  float k2=0.f;
  #pragma unroll
  for (int c=0;c<Cc;c++) k2 += cp[c]*(mse[c] + avar*ivs[c] + lvs[c]);
  kl += 0.5f*k2 - 0.5f*(float)Dkc*(1.0f+alv);
  float tot = blockSum<512>(kl, red);
  if (l==0) atomicAdd(&klOut[b], tot*(1.0f/((float)Hc*Lc)));
  if (HEAD){
    float bm = blockMax<512>(mx, red);
    if (l==0) atomicMaxF(&g_gmax, bm);
  }
}

// ---------------- div via 4x4 Gram ----------------
__global__ __launch_bounds__(512) void div_fast(const float4* __restrict__ cp, float* __restrict__ divOut){
  int bh = blockIdx.x; int b = bh/Hc;
  __shared__ float red[512];
  float4 p = cp[(size_t)bh*Lc + threadIdx.x];
  float g = p.x*p.x + p.y*p.y + p.z*p.z + p.w*p.w;
  float m[10] = {p.x*p.x, p.x*p.y, p.x*p.z, p.x*p.w,
                 p.y*p.y, p.y*p.z, p.y*p.w,
                 p.z*p.z, p.z*p.w, p.w*p.w};
  float dterm = 1.25f*(g-1.0f)*(g-1.0f) - 0.75f*g*g;
  float Ms[10];
  #pragma unroll
  for (int i=0;i<10;i++) Ms[i] = blockSum<512>(m[i], red);
  float dsum = blockSum<512>(dterm, red);
  if (threadIdx.x == 0){
    float frob = Ms[0]*Ms[0] + Ms[4]*Ms[4] + Ms[7]*Ms[7] + Ms[9]*Ms[9]
      + 2.0f*(Ms[1]*Ms[1] + Ms[2]*Ms[2] + Ms[3]*Ms[3] + Ms[5]*Ms[5] + Ms[6]*Ms[6] + Ms[8]*Ms[8]);
    atomicAdd(&divOut[b], (0.75f*frob + dsum) * (1.0f/((float)Hc*Lc*Lc)));
  }
}

// ---------------- fused softmax*mask + renorm + head-mean ----------------
__global__ __launch_bounds__(512) void softmax_mean(float* __restrict__ am){
  __shared__ float mat[16][512];
  int r = blockIdx.x;
  int b = r >> 9, q = r & 511;
  int tid = threadIdx.x, w = tid >> 5, lane = tid & 31;
  int bh = b*Hc + w;
  float* row = g_attn + ((size_t)bh*Lc + q)*Lc;
  const float4* cp4 = ((const float4*)g_cpq) + (size_t)bh*Lc;
  float4 cq = cp4[q];
  float s[16];
  #pragma unroll
  for (int t=0;t<16;t++) s[t] = row[lane + t*32];
  float mx = -3.0e38f;
  #pragma unroll
  for (int t=0;t<16;t++) mx = fmaxf(mx, s[t]);
  mx = wmax32(mx);
  float es = 0.f;
  #pragma unroll
  for (int t=0;t<16;t++){ s[t] = fexp(s[t]-mx); es += s[t]; }
  es = wsum32(es);
  float inv_se = 1.0f/es;
  float ts = 0.f;
  #pragma unroll
  for (int t=0;t<16;t++){
    float4 ck = cp4[lane + t*32];
    float m = cq.x*ck.x + cq.y*ck.y + cq.z*ck.z + cq.w*ck.w;
    s[t] = s[t]*inv_se*m;
    ts += s[t];
  }
  ts = wsum32(ts);
  float inv = 1.0f/(ts + 1e-6f);
  #pragma unroll
  for (int t=0;t<16;t++){
    float f = s[t]*inv;
    row[lane + t*32] = f;
    mat[w][lane + t*32] = f;
  }
  __syncthreads();
  float sum = 0.f;
  #pragma unroll
  for (int h=0;h<16;h++) sum += mat[h][tid];
  am[(size_t)r*Lc + tid] = sum * (1.0f/16.0f);
}

__global__ __launch_bounds__(512) void pdf_wsum_kernel(){
  int bh=blockIdx.x; int l=threadIdx.x;
  __shared__ float red[512];
  float gm = g_gmax;
  int base = (bh*Lc+l)*Cc;
  float p=0.f;
  #pragma unroll
  for (int c=0;c<Cc;c++) p += fexp(g_lpdf[base+c]-gm);
  g_pdf[bh*Lc+l]=p;
  #pragma unroll
  for (int c=0;c<Cc;c++){
    float s = blockSum<512>(g_cph[base+c]*p, red);
    if (l==0) g_wsum[bh*Cc+c]=s;
  }
}

__global__ void mi_kernel(float* __restrict__ miOut){
  int bl=blockIdx.x; int b=bl>>9, l=bl&511;
  int i=threadIdx.x;
  float cpv[Cc]={0,0,0,0}, mp[Cc]={0,0,0,0};
  if (i<Hc){
    int base = ((b*Hc+i)*Lc+l)*Cc;
    float pd = g_pdf[(b*Hc+i)*Lc+l];
    #pragma unroll
    for (int c=0;c<Cc;c++){
      cpv[c]=g_cph[base+c];
      mp[c]=cpv[c]*pd/fmaxf(g_wsum[(b*Hc+i)*Cc+c],1e-6f);
    }
  }
  float acc=0.f;
  for (int j=0;j<Hc;j++){
    float c0=__shfl_sync(0xffffffffu,cpv[0],j);
    float c1=__shfl_sync(0xffffffffu,cpv[1],j);
    float c2=__shfl_sync(0xffffffffu,cpv[2],j);
    float c3=__shfl_sync(0xffffffffu,cpv[3],j);
    if (i<Hc && i!=j){
      float p = fminf(mp[0]*c0+mp[1]*c1+mp[2]*c2+mp[3]*c3, 1.0f);
      acc += logf(1.0f-p+1e-6f);
    }
  }
  #pragma unroll
  for (int o=16;o>0;o>>=1) acc += __shfl_down_sync(0xffffffffu,acc,o);
  if (i==0) atomicAdd(&miOut[b], acc*(-10.0f/((float)Lc*Hc*Hc)));
}

__global__ __launch_bounds__(512) void diag_kernel(float* __restrict__ miOut){
  int bh=blockIdx.x; int b=bh>>4;
  __shared__ float4 cps[Lc];
  __shared__ float red[512];
  for (int i=threadIdx.x;i<Lc;i+=512) cps[i]=((const float4*)g_cph)[(size_t)bh*Lc+i];
  __syncthreads();
  int q=threadIdx.x;
  float4 a=cps[q];
  float s=0.f, dq=0.f;
  for (int k=0;k<Lc;k++){
    float4 c=cps[k];
    float g=a.x*c.x+a.y*c.y+a.z*c.z+a.w*c.w;
    if (k==q) dq=g;
    s += fexp(g);
  }
  float tot = blockSum<512>(dq-logf(s), red);
  if (threadIdx.x==0) atomicAdd(&miOut[b], -tot/((float)Hc*Lc));
}

extern "C" void kernel_launch(void* const* d_in, const int* in_sizes, int n_in,
                              void* d_out, int out_size){
  const float *query=(const float*)d_in[0], *key=(const float*)d_in[1], *value=(const float*)d_in[2];
  const float *Wq=(const float*)d_in[3], *bq=(const float*)d_in[4];
  const float *Wk=(const float*)d_in[5], *bk=(const float*)d_in[6];
  const float *Wv=(const float*)d_in[7], *bv=(const float*)d_in[8];
  const float *Wo=(const float*)d_in[9], *bo=(const float*)d_in[10];
  const float *Wsem=(const float*)d_in[11], *bsem=(const float*)d_in[12];
  const float *Whead=(const float*)d_in[13], *bhead=(const float*)d_in[14];
  const float *tmu=(const float*)d_in[15], *tlv=(const float*)d_in[16], *tlp=(const float*)d_in[17];
  const float *hmu=(const float*)d_in[18], *hlv=(const float*)d_in[19], *hlp=(const float*)d_in[20];
  float* out = (float*)d_out;
  float* am  = out + OUT_N;
  float* kl  = out + KL_OFF;
  float* dv  = out + KL_OFF + 8;
  float* mi  = out + KL_OFF + 16;

  float *pq,*pk,*pv,*pvt,*pctx,*pwt,*pwt2,*pwt3,*pwt4,*palv,*palvh,*pcpq,*pcph,*plpdf;
  cudaGetSymbolAddress((void**)&pq, g_q);
  cudaGetSymbolAddress((void**)&pk, g_k);
  cudaGetSymbolAddress((void**)&pv, g_v);
  cudaGetSymbolAddress((void**)&pvt, g_vt);
  cudaGetSymbolAddress((void**)&pctx, g_ctx);
  cudaGetSymbolAddress((void**)&pwt, g_wt);
  cudaGetSymbolAddress((void**)&pwt2, g_wt2);
  cudaGetSymbolAddress((void**)&pwt3, g_wt3);
  cudaGetSymbolAddress((void**)&pwt4, g_wt4);
  cudaGetSymbolAddress((void**)&palv, g_alv);
  cudaGetSymbolAddress((void**)&palvh, g_alvh);
  cudaGetSymbolAddress((void**)&pcpq, g_cpq);
  cudaGetSymbolAddress((void**)&pcph, g_cph);
  cudaGetSymbolAddress((void**)&plpdf, g_lpdf);

  cudaFuncSetAttribute(gemm_mma, cudaFuncAttributeMaxDynamicSharedMemorySize, SMEM_MMA);
  cudaFuncSetAttribute(scores_mma, cudaFuncAttributeMaxDynamicSharedMemorySize, SMEM_SC);
  cudaFuncSetAttribute(ctx_mma, cudaFuncAttributeMaxDynamicSharedMemorySize, SMEM_CTX);

  int M = Bc*Lc;
  dim3 gt(32, 32), bt(32, 8);
  dim3 gg(Dmod/128, M/128);

  zero_kernel<<<1, 32>>>(kl);
  transpose_kernel<<<gt, bt>>>(Wq, pwt);
  transpose_kernel<<<gt, bt>>>(Wk, pwt2);
  transpose_kernel<<<gt, bt>>>(Wv, pwt3);
  transpose_kernel<<<gt, bt>>>(Wo, pwt4);
  gemm_mma<<<gg, 256, SMEM_MMA>>>(query, pwt, bq, pq);
  gemm_mma<<<gg, 256, SMEM_MMA>>>(key, pwt2, bk, pk);
  gemm_mma<<<gg, 256, SMEM_MMA>>>(value, pwt3, bv, pv);
  transpose_v<<<dim3(Bc*Hc, Lc/32, Dkc/32), bt>>>(pv, pvt);
  gemm16_kernel<<<M*16/256, 256>>>(pq, Wsem, bsem, palv);
  cluster_kernel<false><<<Bc*Hc, 512>>>(pq, palv, tmu, tlv, tlp, pcpq, nullptr, kl);
  div_fast<<<Bc*Hc, 512>>>((const float4*)pcpq, dv);
  scores_mma<<<dim3(Bc*Hc, Lc/128, Lc/128), 256, SMEM_SC>>>();
  softmax_mean<<<Bc*Lc, 512>>>(am);
  ctx_mma<<<dim3(Bc*Hc, Lc/128), 256, SMEM_CTX>>>(pvt);
  gemm16_kernel<<<M*16/256, 256>>>(pctx, Whead, bhead, palvh);
  cluster_kernel<true><<<Bc*Hc, 512>>>(pctx, palvh, hmu, hlv, hlp, pcph, plpdf, kl);
  div_fast<<<Bc*Hc, 512>>>((const float4*)pcph, dv);
  pdf_wsum_kernel<<<Bc*Hc, 512>>>();
  mi_kernel<<<Bc*Lc, 32>>>(mi);
  diag_kernel<<<Bc*Hc, 512>>>(mi);
  gemm_mma<<<gg, 256, SMEM_MMA>>>(pctx, pwt4, bo, out);
}